// round 4
// baseline (speedup 1.0000x reference)
#include <cuda_runtime.h>
#include <math.h>

#define BB     8
#define M_TOT  1026
#define CC     384
#define N1     513
#define HH     6
#define DD     64
#define BHN    (BB*HH)      // 48
#define MROWS  (BB*N1)      // 4104
#define MROWS2 (BB*M_TOT)   // 8208

#define SW     580          // smem score-row stride (floats); 580*4 % 16 == 0
#define KPAD   544          // 17 * 32, covers 513 with zero-prob padding

// ---- scratch (device globals; no cudaMalloc allowed) ----
__device__ int   g_sel;
__device__ float g_Q [MROWS*CC];
__device__ float g_K [MROWS*CC];
__device__ float g_V1[MROWS*CC];
__device__ float g_V2[MROWS*CC];
__device__ float g_O [MROWS2*CC];           // pre-Wo activations

// ------------------------------------------------------------------
// 0) straight-through gumbel selection: argmax(weights + noise)
// ------------------------------------------------------------------
__global__ void select_kernel(const float* __restrict__ w,
                              const float* __restrict__ g) {
    float best = w[0] + g[0];
    int bi = 0;
    #pragma unroll
    for (int i = 1; i < 4; i++) {
        float v = w[i] + g[i];
        if (v > best) { best = v; bi = i; }
    }
    g_sel = bi;
}

// ------------------------------------------------------------------
// 1) input projections: Q (selected), K (selected), V1, V2
//    batched via blockIdx.z; GEMM (4104 x 384 x 384), BM=128 BN=64 BK=32
// ------------------------------------------------------------------
__global__ __launch_bounds__(256)
void proj_kernel(const float* __restrict__ x,
                 const float* Wq1, const float* bq1,
                 const float* Wq2, const float* bq2,
                 const float* Wk1, const float* bk1,
                 const float* Wk2, const float* bk2,
                 const float* Wv1, const float* bv1,
                 const float* Wv2, const float* bv2) {
    const int job = blockIdx.z;
    const int sel = g_sel;
    const float* W; const float* bias; float* OUT; int off;
    if (job == 0) { int qs = sel >> 1; W = qs ? Wq2 : Wq1; bias = qs ? bq2 : bq1; OUT = g_Q;  off = qs ? N1 : 0; }
    else if (job == 1) { int ks = sel & 1; W = ks ? Wk2 : Wk1; bias = ks ? bk2 : bk1; OUT = g_K;  off = ks ? N1 : 0; }
    else if (job == 2) { W = Wv1; bias = bv1; OUT = g_V1; off = 0;  }
    else               { W = Wv2; bias = bv2; OUT = g_V2; off = N1; }

    __shared__ float As[32][132];   // As[k][m]
    __shared__ float Bs[32][64];

    const int m0 = blockIdx.y * 128, n0 = blockIdx.x * 64;
    const int tid = threadIdx.x;
    const int ty = tid >> 4, tx = tid & 15;
    float acc[8][4];
    #pragma unroll
    for (int i = 0; i < 8; i++)
        #pragma unroll
        for (int j = 0; j < 4; j++) acc[i][j] = 0.f;

    for (int k0 = 0; k0 < CC; k0 += 32) {
        #pragma unroll
        for (int t = 0; t < 16; t++) {
            int idx = tid + t * 256;
            int mm = idx >> 5, kk = idx & 31;
            int m = m0 + mm;
            float v = 0.f;
            if (m < MROWS) {
                int b = m / N1, n = m % N1;
                v = x[((size_t)b * M_TOT + n + off) * CC + k0 + kk];
            }
            As[kk][mm] = v;
        }
        #pragma unroll
        for (int t = 0; t < 8; t++) {
            int idx = tid + t * 256;
            int kk = idx >> 6, nn = idx & 63;
            Bs[kk][nn] = W[(k0 + kk) * CC + n0 + nn];
        }
        __syncthreads();
        #pragma unroll
        for (int kk = 0; kk < 32; kk++) {
            float a[8], bb[4];
            #pragma unroll
            for (int i = 0; i < 8; i++) a[i] = As[kk][ty * 8 + i];
            #pragma unroll
            for (int j = 0; j < 4; j++) bb[j] = Bs[kk][tx * 4 + j];
            #pragma unroll
            for (int i = 0; i < 8; i++)
                #pragma unroll
                for (int j = 0; j < 4; j++) acc[i][j] += a[i] * bb[j];
        }
        __syncthreads();
    }
    #pragma unroll
    for (int i = 0; i < 8; i++) {
        int m = m0 + ty * 8 + i;
        if (m >= MROWS) continue;
        #pragma unroll
        for (int j = 0; j < 4; j++) {
            int n = n0 + tx * 4 + j;
            OUT[(size_t)m * CC + n] = acc[i][j] + bias[n];
        }
    }
}

// ------------------------------------------------------------------
// 2) fused attention: per (bh, q-tile of 64):
//    phase A: S[64][544..576] = scale * Q Kt   (entire strip in smem)
//    phase B: in-smem row softmax (1/sum deferred to epilogue)
//    phase C: O = P @ [V1|V2]  (64 x 128), scaled by 1/sum at write
//    smem: S 64*580 + Qs 64*68 + Ks 64*68 + Vs 32*132 + inv 64 = ~195.8 KB
// ------------------------------------------------------------------
__global__ __launch_bounds__(256)
void fused_attn_kernel() {
    extern __shared__ float sm[];
    float* Ssm = sm;                       // [64][SW]
    float* Qs  = Ssm + 64 * SW;            // [64][68]  (Qs[d][i])
    float* Ks  = Qs  + 64 * 68;            // [64][68]  (Ks[d][j])
    float* Vs  = Ks  + 64 * 68;            // [32][132]
    float* inv = Vs  + 32 * 132;           // [64]

    const int bh = blockIdx.y;
    const int b = bh / HH, hh = bh % HH;
    const int q0 = blockIdx.x * 64;
    const int tid = threadIdx.x;
    const int ty = tid >> 4, tx = tid & 15;

    // ---- load Q tile (transposed) ----
    #pragma unroll
    for (int t = 0; t < 16; t++) {
        int idx = tid + t * 256;
        int r = idx >> 6, c = idx & 63;
        int qi = q0 + r;
        Qs[c * 68 + r] = (qi < N1) ? g_Q[((size_t)b * N1 + qi) * CC + hh * DD + c] : 0.f;
    }
    __syncthreads();

    // ---- phase A: scores into smem strip ----
    for (int jt = 0; jt < 9; jt++) {
        const int j0 = jt * 64;
        #pragma unroll
        for (int t = 0; t < 16; t++) {
            int idx = tid + t * 256;
            int r = idx >> 6, c = idx & 63;
            int kj = j0 + r;
            Ks[c * 68 + r] = (kj < N1) ? g_K[((size_t)b * N1 + kj) * CC + hh * DD + c] : 0.f;
        }
        __syncthreads();

        float acc[4][4];
        #pragma unroll
        for (int i = 0; i < 4; i++)
            #pragma unroll
            for (int j = 0; j < 4; j++) acc[i][j] = 0.f;

        #pragma unroll
        for (int kk = 0; kk < 64; kk++) {
            float4 a  = *(const float4*)&Qs[kk * 68 + ty * 4];
            float4 bv = *(const float4*)&Ks[kk * 68 + tx * 4];
            const float av[4] = {a.x, a.y, a.z, a.w};
            const float bw[4] = {bv.x, bv.y, bv.z, bv.w};
            #pragma unroll
            for (int i = 0; i < 4; i++)
                #pragma unroll
                for (int j = 0; j < 4; j++) acc[i][j] += av[i] * bw[j];
        }

        const float scale = 0.125f;   // 64^-0.5
        #pragma unroll
        for (int i = 0; i < 4; i++) {
            int q = ty * 4 + i;
            float4 w;
            float o[4];
            #pragma unroll
            for (int j = 0; j < 4; j++) {
                int jc = j0 + tx * 4 + j;
                o[j] = (jc < N1) ? acc[i][j] * scale : -1e30f;
            }
            w.x = o[0]; w.y = o[1]; w.z = o[2]; w.w = o[3];
            *(float4*)&Ssm[q * SW + j0 + tx * 4] = w;
        }
        __syncthreads();
    }

    // ---- phase B: row softmax (exp in place; 1/sum stashed) ----
    {
        const int warp = tid >> 5, lane = tid & 31;
        #pragma unroll
        for (int rr = 0; rr < 8; rr++) {
            int r = warp * 8 + rr;
            float v[17];
            float m = -1e30f;
            #pragma unroll
            for (int t = 0; t < 17; t++) {
                v[t] = Ssm[r * SW + lane + 32 * t];
                m = fmaxf(m, v[t]);
            }
            #pragma unroll
            for (int o = 16; o > 0; o >>= 1)
                m = fmaxf(m, __shfl_xor_sync(0xffffffffu, m, o));
            float s = 0.f;
            #pragma unroll
            for (int t = 0; t < 17; t++) {
                float e = __expf(v[t] - m);
                s += e;
                Ssm[r * SW + lane + 32 * t] = e;
            }
            #pragma unroll
            for (int o = 16; o > 0; o >>= 1)
                s += __shfl_xor_sync(0xffffffffu, s, o);
            if (lane == 0) inv[r] = 1.f / s;
        }
    }
    __syncthreads();

    // ---- phase C: P @ [V1|V2] ----
    float oacc[4][8];
    #pragma unroll
    for (int i = 0; i < 4; i++)
        #pragma unroll
        for (int j = 0; j < 8; j++) oacc[i][j] = 0.f;

    for (int k0 = 0; k0 < KPAD; k0 += 32) {
        #pragma unroll
        for (int t = 0; t < 16; t++) {
            int idx = tid + t * 256;
            int kk = idx >> 7, j = idx & 127;
            int ki = k0 + kk;
            float v = 0.f;
            if (ki < N1) {
                if (j < 64) v = g_V1[((size_t)b * N1 + ki) * CC + hh * DD + j];
                else        v = g_V2[((size_t)b * N1 + ki) * CC + hh * DD + (j - 64)];
            }
            Vs[kk * 132 + j] = v;
        }
        __syncthreads();

        #pragma unroll
        for (int kk = 0; kk < 32; kk++) {
            float a[4];
            #pragma unroll
            for (int i = 0; i < 4; i++) a[i] = Ssm[(ty * 4 + i) * SW + k0 + kk];
            float4 b0 = *(const float4*)&Vs[kk * 132 + tx * 8];
            float4 b1 = *(const float4*)&Vs[kk * 132 + tx * 8 + 4];
            const float bw[8] = {b0.x, b0.y, b0.z, b0.w, b1.x, b1.y, b1.z, b1.w};
            #pragma unroll
            for (int i = 0; i < 4; i++)
                #pragma unroll
                for (int j = 0; j < 8; j++) oacc[i][j] += a[i] * bw[j];
        }
        __syncthreads();
    }

    // ---- epilogue: scale by 1/sum and write g_O ----
    #pragma unroll
    for (int i = 0; i < 4; i++) {
        int q = ty * 4 + i;
        int qi = q0 + q;
        if (qi >= N1) continue;
        float sc = inv[q];
        int jj0 = tx * 8;
        int row = (jj0 < 64) ? qi : (N1 + qi);
        int c = hh * DD + (jj0 & 63);
        float4 o0, o1;
        o0.x = oacc[i][0] * sc; o0.y = oacc[i][1] * sc;
        o0.z = oacc[i][2] * sc; o0.w = oacc[i][3] * sc;
        o1.x = oacc[i][4] * sc; o1.y = oacc[i][5] * sc;
        o1.z = oacc[i][6] * sc; o1.w = oacc[i][7] * sc;
        float* dst = &g_O[((size_t)b * M_TOT + row) * CC + c];
        *(float4*)dst       = o0;
        *(float4*)(dst + 4) = o1;
    }
}

// ------------------------------------------------------------------
// 3) output projection: out = g_O (8208x384) @ Wo + bo
// ------------------------------------------------------------------
__global__ __launch_bounds__(256)
void final_kernel(const float* __restrict__ Wo,
                  const float* __restrict__ bo,
                  float* __restrict__ out) {
    __shared__ float As[32][132];
    __shared__ float Bs[32][64];

    const int m0 = blockIdx.y * 128, n0 = blockIdx.x * 64;
    const int tid = threadIdx.x;
    const int ty = tid >> 4, tx = tid & 15;
    float acc[8][4];
    #pragma unroll
    for (int i = 0; i < 8; i++)
        #pragma unroll
        for (int j = 0; j < 4; j++) acc[i][j] = 0.f;

    for (int k0 = 0; k0 < CC; k0 += 32) {
        #pragma unroll
        for (int t = 0; t < 16; t++) {
            int idx = tid + t * 256;
            int mm = idx >> 5, kk = idx & 31;
            int m = m0 + mm;
            As[kk][mm] = (m < MROWS2) ? g_O[(size_t)m * CC + k0 + kk] : 0.f;
        }
        #pragma unroll
        for (int t = 0; t < 8; t++) {
            int idx = tid + t * 256;
            int kk = idx >> 6, nn = idx & 63;
            Bs[kk][nn] = Wo[(k0 + kk) * CC + n0 + nn];
        }
        __syncthreads();
        #pragma unroll
        for (int kk = 0; kk < 32; kk++) {
            float a[8], bb[4];
            #pragma unroll
            for (int i = 0; i < 8; i++) a[i] = As[kk][ty * 8 + i];
            #pragma unroll
            for (int j = 0; j < 4; j++) bb[j] = Bs[kk][tx * 4 + j];
            #pragma unroll
            for (int i = 0; i < 8; i++)
                #pragma unroll
                for (int j = 0; j < 4; j++) acc[i][j] += a[i] * bb[j];
        }
        __syncthreads();
    }
    #pragma unroll
    for (int i = 0; i < 8; i++) {
        int m = m0 + ty * 8 + i;
        if (m >= MROWS2) continue;
        #pragma unroll
        for (int j = 0; j < 4; j++) {
            int n = n0 + tx * 4 + j;
            out[(size_t)m * CC + n] = acc[i][j] + bo[n];
        }
    }
}

// ------------------------------------------------------------------
extern "C" void kernel_launch(void* const* d_in, const int* in_sizes, int n_in,
                              void* d_out, int out_size) {
    const float* x   = (const float*)d_in[0];
    const float* Wq1 = (const float*)d_in[1];  const float* bq1 = (const float*)d_in[2];
    const float* Wq2 = (const float*)d_in[3];  const float* bq2 = (const float*)d_in[4];
    const float* Wk1 = (const float*)d_in[5];  const float* bk1 = (const float*)d_in[6];
    const float* Wk2 = (const float*)d_in[7];  const float* bk2 = (const float*)d_in[8];
    const float* Wv1 = (const float*)d_in[9];  const float* bv1 = (const float*)d_in[10];
    const float* Wv2 = (const float*)d_in[11]; const float* bv2 = (const float*)d_in[12];
    const float* Wo  = (const float*)d_in[13]; const float* bo  = (const float*)d_in[14];
    const float* wts = (const float*)d_in[15]; const float* gum = (const float*)d_in[16];
    float* out = (float*)d_out;

    const int fused_smem = (64 * SW + 64 * 68 + 64 * 68 + 32 * 132 + 64) * 4;
    static int smem_set = 0;
    if (!smem_set) {
        cudaFuncSetAttribute(fused_attn_kernel,
                             cudaFuncAttributeMaxDynamicSharedMemorySize,
                             fused_smem);
        smem_set = 1;
    }

    select_kernel<<<1, 1>>>(wts, gum);

    dim3 pg(CC / 64, (MROWS + 127) / 128, 4);               // 6 x 33 x 4
    proj_kernel<<<pg, 256>>>(x, Wq1, bq1, Wq2, bq2, Wk1, bk1, Wk2, bk2,
                             Wv1, bv1, Wv2, bv2);

    fused_attn_kernel<<<dim3((N1 + 63) / 64, BHN), 256, fused_smem>>>();  // 9 x 48

    final_kernel<<<dim3(CC / 64, (MROWS2 + 127) / 128, 1), 256>>>(Wo, bo, out);
}

// round 5
// speedup vs baseline: 1.1168x; 1.1168x over previous
#include <cuda_runtime.h>
#include <math.h>

#define BB     8
#define M_TOT  1026
#define CC     384
#define N1     513
#define HH     6
#define DD     64
#define BHN    (BB*HH)      // 48
#define MROWS  (BB*N1)      // 4104
#define MROWS2 (BB*M_TOT)   // 8208

// ---- scratch (device globals; no cudaMalloc allowed) ----
__device__ int   g_sel;
__device__ float g_Q [MROWS*CC];
__device__ float g_K [MROWS*CC];
__device__ float g_V1[MROWS*CC];
__device__ float g_V2[MROWS*CC];
__device__ float g_S [(size_t)BHN*N1*N1];   // raw scores, ~50.5 MB (L2-resident)
__device__ float g_O [MROWS2*CC];           // pre-Wo activations

// ------------------------------------------------------------------
// 0) straight-through gumbel selection: argmax(weights + noise)
// ------------------------------------------------------------------
__global__ void select_kernel(const float* __restrict__ w,
                              const float* __restrict__ g) {
    float best = w[0] + g[0];
    int bi = 0;
    #pragma unroll
    for (int i = 1; i < 4; i++) {
        float v = w[i] + g[i];
        if (v > best) { best = v; bi = i; }
    }
    g_sel = bi;
}

// ------------------------------------------------------------------
// 1) input projections: GEMM (4104 x 384 x 384), BM=128 BN=128 BK=32,
//    8x8 accumulators, batched over 4 jobs via blockIdx.z
// ------------------------------------------------------------------
__global__ __launch_bounds__(256)
void proj_kernel(const float* __restrict__ x,
                 const float* Wq1, const float* bq1,
                 const float* Wq2, const float* bq2,
                 const float* Wk1, const float* bk1,
                 const float* Wk2, const float* bk2,
                 const float* Wv1, const float* bv1,
                 const float* Wv2, const float* bv2) {
    const int job = blockIdx.z;
    const int sel = g_sel;
    const float* W; const float* bias; float* OUT; int off;
    if (job == 0) { int qs = sel >> 1; W = qs ? Wq2 : Wq1; bias = qs ? bq2 : bq1; OUT = g_Q;  off = qs ? N1 : 0; }
    else if (job == 1) { int ks = sel & 1; W = ks ? Wk2 : Wk1; bias = ks ? bk2 : bk1; OUT = g_K;  off = ks ? N1 : 0; }
    else if (job == 2) { W = Wv1; bias = bv1; OUT = g_V1; off = 0;  }
    else               { W = Wv2; bias = bv2; OUT = g_V2; off = N1; }

    __shared__ float As[32][132];   // As[k][m]
    __shared__ float Bs[32][128];   // Bs[k][n]

    const int m0 = blockIdx.y * 128, n0 = blockIdx.x * 128;
    const int tid = threadIdx.x;
    const int ty = tid >> 4, tx = tid & 15;
    float acc[8][8];
    #pragma unroll
    for (int i = 0; i < 8; i++)
        #pragma unroll
        for (int j = 0; j < 8; j++) acc[i][j] = 0.f;

    for (int k0 = 0; k0 < CC; k0 += 32) {
        #pragma unroll
        for (int t = 0; t < 16; t++) {
            int idx = tid + t * 256;
            int mm = idx >> 5, kk = idx & 31;
            int m = m0 + mm;
            float v = 0.f;
            if (m < MROWS) {
                int b = m / N1, n = m % N1;
                v = x[((size_t)b * M_TOT + n + off) * CC + k0 + kk];
            }
            As[kk][mm] = v;
        }
        #pragma unroll
        for (int t = 0; t < 16; t++) {
            int idx = tid + t * 256;
            int kk = idx >> 7, nn = idx & 127;
            Bs[kk][nn] = W[(k0 + kk) * CC + n0 + nn];
        }
        __syncthreads();
        #pragma unroll
        for (int kk = 0; kk < 32; kk++) {
            float4 a0 = *(const float4*)&As[kk][ty * 8];
            float4 a1 = *(const float4*)&As[kk][ty * 8 + 4];
            float4 b0 = *(const float4*)&Bs[kk][tx * 8];
            float4 b1 = *(const float4*)&Bs[kk][tx * 8 + 4];
            const float a[8]  = {a0.x, a0.y, a0.z, a0.w, a1.x, a1.y, a1.z, a1.w};
            const float bb[8] = {b0.x, b0.y, b0.z, b0.w, b1.x, b1.y, b1.z, b1.w};
            #pragma unroll
            for (int i = 0; i < 8; i++)
                #pragma unroll
                for (int j = 0; j < 8; j++) acc[i][j] += a[i] * bb[j];
        }
        __syncthreads();
    }
    #pragma unroll
    for (int i = 0; i < 8; i++) {
        int m = m0 + ty * 8 + i;
        if (m >= MROWS) continue;
        float* dst = &OUT[(size_t)m * CC + n0 + tx * 8];
        const float* bp = &bias[n0 + tx * 8];
        float4 o0, o1;
        o0.x = acc[i][0] + bp[0]; o0.y = acc[i][1] + bp[1];
        o0.z = acc[i][2] + bp[2]; o0.w = acc[i][3] + bp[3];
        o1.x = acc[i][4] + bp[4]; o1.y = acc[i][5] + bp[5];
        o1.z = acc[i][6] + bp[6]; o1.w = acc[i][7] + bp[7];
        *(float4*)dst       = o0;
        *(float4*)(dst + 4) = o1;
    }
}

// ------------------------------------------------------------------
// 2) scores: S[bh][i][j] = scale * dot(Q[b,i,h,:], K[b,j,h,:])  (d=64)
// ------------------------------------------------------------------
__global__ __launch_bounds__(256)
void scores_kernel() {
    const int bh = blockIdx.z;
    const int b = bh / HH, hh = bh % HH;
    const int i0 = blockIdx.y * 64, j0 = blockIdx.x * 64;

    __shared__ float Qs[64][68];   // Qs[d][i]
    __shared__ float Ks[64][68];   // Ks[d][j]

    const int tid = threadIdx.x;
    const int ty = tid >> 4, tx = tid & 15;

    #pragma unroll
    for (int t = 0; t < 16; t++) {
        int idx = tid + t * 256;
        int r = idx >> 6, c = idx & 63;
        int qi = i0 + r;
        Qs[c][r] = (qi < N1) ? g_Q[((size_t)b * N1 + qi) * CC + hh * DD + c] : 0.f;
        int kj = j0 + r;
        Ks[c][r] = (kj < N1) ? g_K[((size_t)b * N1 + kj) * CC + hh * DD + c] : 0.f;
    }
    __syncthreads();

    float acc[4][4];
    #pragma unroll
    for (int i = 0; i < 4; i++)
        #pragma unroll
        for (int j = 0; j < 4; j++) acc[i][j] = 0.f;

    #pragma unroll
    for (int kk = 0; kk < 64; kk++) {
        float4 a  = *(const float4*)&Qs[kk][ty * 4];
        float4 bv = *(const float4*)&Ks[kk][tx * 4];
        const float av[4] = {a.x, a.y, a.z, a.w};
        const float bw[4] = {bv.x, bv.y, bv.z, bv.w};
        #pragma unroll
        for (int i = 0; i < 4; i++)
            #pragma unroll
            for (int j = 0; j < 4; j++) acc[i][j] += av[i] * bw[j];
    }

    const float scale = 0.125f;  // 64^-0.5
    const size_t base = (size_t)bh * N1 * N1;
    #pragma unroll
    for (int i = 0; i < 4; i++) {
        int qi = i0 + ty * 4 + i;
        if (qi >= N1) continue;
        #pragma unroll
        for (int j = 0; j < 4; j++) {
            int kj = j0 + tx * 4 + j;
            if (kj >= N1) continue;
            g_S[base + (size_t)qi * N1 + kj] = acc[i][j] * scale;
        }
    }
}

// ------------------------------------------------------------------
// 3) fused softmax + AV: per (bh, q-tile of 64):
//    pre-pass: row max + exp-sum straight from raw g_S (L2)
//    main: As[kk][q] = exp(S - m[q]) during tile fill, PV accumulate,
//          epilogue scaled by 1/sum
// ------------------------------------------------------------------
__global__ __launch_bounds__(256)
void av_kernel() {
    const int bh = blockIdx.y;
    const int b = bh / HH, hh = bh % HH;
    const int q0 = blockIdx.x * 64;

    __shared__ float As[32][68];    // As[k][q] (already exp'd)
    __shared__ float Vs[32][132];   // Vs[k][j]  (j<64: V1, j>=64: V2)
    __shared__ float mx[64];
    __shared__ float inv[64];

    const int tid = threadIdx.x;
    const int ty = tid >> 4, tx = tid & 15;
    const size_t Sbase = (size_t)bh * N1 * N1;

    // ---- softmax stats pre-pass: warp w owns rows w*8..w*8+7 ----
    {
        const int warp = tid >> 5, lane = tid & 31;
        #pragma unroll
        for (int rr = 0; rr < 8; rr++) {
            int r = warp * 8 + rr;
            int qi = q0 + r;
            if (qi < N1) {
                const float* p = g_S + Sbase + (size_t)qi * N1;
                float v[17];
                float m = -1e30f;
                #pragma unroll
                for (int t = 0; t < 17; t++) {
                    int j = lane + 32 * t;
                    v[t] = (j < N1) ? p[j] : -1e30f;
                    m = fmaxf(m, v[t]);
                }
                #pragma unroll
                for (int o = 16; o > 0; o >>= 1)
                    m = fmaxf(m, __shfl_xor_sync(0xffffffffu, m, o));
                float s = 0.f;
                #pragma unroll
                for (int t = 0; t < 17; t++) s += __expf(v[t] - m);
                #pragma unroll
                for (int o = 16; o > 0; o >>= 1)
                    s += __shfl_xor_sync(0xffffffffu, s, o);
                if (lane == 0) { mx[r] = m; inv[r] = 1.f / s; }
            } else if (lane == 0) { mx[r] = 0.f; inv[r] = 0.f; }
        }
    }
    __syncthreads();

    float oacc[4][8];
    #pragma unroll
    for (int i = 0; i < 4; i++)
        #pragma unroll
        for (int j = 0; j < 8; j++) oacc[i][j] = 0.f;

    for (int k0 = 0; k0 < 544; k0 += 32) {
        #pragma unroll
        for (int t = 0; t < 8; t++) {
            int idx = tid + t * 256;
            int q = idx >> 5, kk = idx & 31;
            int qi = q0 + q, ki = k0 + kk;
            float v = 0.f;
            if (qi < N1 && ki < N1)
                v = __expf(g_S[Sbase + (size_t)qi * N1 + ki] - mx[q]);
            As[kk][q] = v;
        }
        #pragma unroll
        for (int t = 0; t < 16; t++) {
            int idx = tid + t * 256;
            int kk = idx >> 7, j = idx & 127;
            int ki = k0 + kk;
            float v = 0.f;
            if (ki < N1) {
                if (j < 64) v = g_V1[((size_t)b * N1 + ki) * CC + hh * DD + j];
                else        v = g_V2[((size_t)b * N1 + ki) * CC + hh * DD + (j - 64)];
            }
            Vs[kk][j] = v;
        }
        __syncthreads();

        #pragma unroll
        for (int kk = 0; kk < 32; kk++) {
            float a[4];
            #pragma unroll
            for (int i = 0; i < 4; i++) a[i] = As[kk][ty * 4 + i];
            float4 b0 = *(const float4*)&Vs[kk][tx * 8];
            float4 b1 = *(const float4*)&Vs[kk][tx * 8 + 4];
            const float bw[8] = {b0.x, b0.y, b0.z, b0.w, b1.x, b1.y, b1.z, b1.w};
            #pragma unroll
            for (int i = 0; i < 4; i++)
                #pragma unroll
                for (int j = 0; j < 8; j++) oacc[i][j] += a[i] * bw[j];
        }
        __syncthreads();
    }

    #pragma unroll
    for (int i = 0; i < 4; i++) {
        int q = ty * 4 + i;
        int qi = q0 + q;
        if (qi >= N1) continue;
        float sc = inv[q];
        int jj0 = tx * 8;
        int row = (jj0 < 64) ? qi : (N1 + qi);
        int c = hh * DD + (jj0 & 63);
        float4 o0, o1;
        o0.x = oacc[i][0] * sc; o0.y = oacc[i][1] * sc;
        o0.z = oacc[i][2] * sc; o0.w = oacc[i][3] * sc;
        o1.x = oacc[i][4] * sc; o1.y = oacc[i][5] * sc;
        o1.z = oacc[i][6] * sc; o1.w = oacc[i][7] * sc;
        float* dst = &g_O[((size_t)b * M_TOT + row) * CC + c];
        *(float4*)dst       = o0;
        *(float4*)(dst + 4) = o1;
    }
}

// ------------------------------------------------------------------
// 4) output projection: out = g_O (8208x384) @ Wo + bo,
//    BM=128 BN=128 BK=32, 8x8 accumulators
// ------------------------------------------------------------------
__global__ __launch_bounds__(256)
void final_kernel(const float* __restrict__ Wo,
                  const float* __restrict__ bo,
                  float* __restrict__ out) {
    __shared__ float As[32][132];
    __shared__ float Bs[32][128];

    const int m0 = blockIdx.y * 128, n0 = blockIdx.x * 128;
    const int tid = threadIdx.x;
    const int ty = tid >> 4, tx = tid & 15;
    float acc[8][8];
    #pragma unroll
    for (int i = 0; i < 8; i++)
        #pragma unroll
        for (int j = 0; j < 8; j++) acc[i][j] = 0.f;

    for (int k0 = 0; k0 < CC; k0 += 32) {
        #pragma unroll
        for (int t = 0; t < 16; t++) {
            int idx = tid + t * 256;
            int mm = idx >> 5, kk = idx & 31;
            int m = m0 + mm;
            As[kk][mm] = (m < MROWS2) ? g_O[(size_t)m * CC + k0 + kk] : 0.f;
        }
        #pragma unroll
        for (int t = 0; t < 16; t++) {
            int idx = tid + t * 256;
            int kk = idx >> 7, nn = idx & 127;
            Bs[kk][nn] = Wo[(k0 + kk) * CC + n0 + nn];
        }
        __syncthreads();
        #pragma unroll
        for (int kk = 0; kk < 32; kk++) {
            float4 a0 = *(const float4*)&As[kk][ty * 8];
            float4 a1 = *(const float4*)&As[kk][ty * 8 + 4];
            float4 b0 = *(const float4*)&Bs[kk][tx * 8];
            float4 b1 = *(const float4*)&Bs[kk][tx * 8 + 4];
            const float a[8]  = {a0.x, a0.y, a0.z, a0.w, a1.x, a1.y, a1.z, a1.w};
            const float bb[8] = {b0.x, b0.y, b0.z, b0.w, b1.x, b1.y, b1.z, b1.w};
            #pragma unroll
            for (int i = 0; i < 8; i++)
                #pragma unroll
                for (int j = 0; j < 8; j++) acc[i][j] += a[i] * bb[j];
        }
        __syncthreads();
    }
    #pragma unroll
    for (int i = 0; i < 8; i++) {
        int m = m0 + ty * 8 + i;
        if (m >= MROWS2) continue;
        float* dst = &out[(size_t)m * CC + n0 + tx * 8];
        const float* bp = &bo[n0 + tx * 8];
        float4 o0, o1;
        o0.x = acc[i][0] + bp[0]; o0.y = acc[i][1] + bp[1];
        o0.z = acc[i][2] + bp[2]; o0.w = acc[i][3] + bp[3];
        o1.x = acc[i][4] + bp[4]; o1.y = acc[i][5] + bp[5];
        o1.z = acc[i][6] + bp[6]; o1.w = acc[i][7] + bp[7];
        *(float4*)dst       = o0;
        *(float4*)(dst + 4) = o1;
    }
}

// ------------------------------------------------------------------
extern "C" void kernel_launch(void* const* d_in, const int* in_sizes, int n_in,
                              void* d_out, int out_size) {
    const float* x   = (const float*)d_in[0];
    const float* Wq1 = (const float*)d_in[1];  const float* bq1 = (const float*)d_in[2];
    const float* Wq2 = (const float*)d_in[3];  const float* bq2 = (const float*)d_in[4];
    const float* Wk1 = (const float*)d_in[5];  const float* bk1 = (const float*)d_in[6];
    const float* Wk2 = (const float*)d_in[7];  const float* bk2 = (const float*)d_in[8];
    const float* Wv1 = (const float*)d_in[9];  const float* bv1 = (const float*)d_in[10];
    const float* Wv2 = (const float*)d_in[11]; const float* bv2 = (const float*)d_in[12];
    const float* Wo  = (const float*)d_in[13]; const float* bo  = (const float*)d_in[14];
    const float* wts = (const float*)d_in[15]; const float* gum = (const float*)d_in[16];
    float* out = (float*)d_out;

    select_kernel<<<1, 1>>>(wts, gum);

    dim3 pg(CC / 128, (MROWS + 127) / 128, 4);              // 3 x 33 x 4
    proj_kernel<<<pg, 256>>>(x, Wq1, bq1, Wq2, bq2, Wk1, bk1, Wk2, bk2,
                             Wv1, bv1, Wv2, bv2);

    dim3 sg((N1 + 63) / 64, (N1 + 63) / 64, BHN);           // 9 x 9 x 48
    scores_kernel<<<sg, 256>>>();

    av_kernel<<<dim3((N1 + 63) / 64, BHN), 256>>>();        // 9 x 48

    final_kernel<<<dim3(CC / 128, (MROWS2 + 127) / 128, 1), 256>>>(Wo, bo, out);
}

// round 6
// speedup vs baseline: 1.1647x; 1.0429x over previous
#include <cuda_runtime.h>
#include <math.h>

#define BB     8
#define M_TOT  1026
#define CC     384
#define N1     513
#define HH     6
#define DD     64
#define BHN    (BB*HH)      // 48
#define MROWS  (BB*N1)      // 4104
#define MROWS2 (BB*M_TOT)   // 8208

// ---- scratch (device globals; no cudaMalloc allowed) ----
__device__ int   g_sel;
__device__ float g_Q [MROWS*CC];
__device__ float g_K [MROWS*CC];
__device__ float g_V1[MROWS*CC];
__device__ float g_V2[MROWS*CC];
__device__ float g_S [(size_t)BHN*N1*N1];   // scores -> exp'd scores (~50.5MB, L2)
__device__ float g_inv[BHN*N1];             // 1/rowsum
__device__ float g_O [MROWS2*CC];           // pre-Wo activations

// ------------------------------------------------------------------
// 0) straight-through gumbel selection: argmax(weights + noise)
// ------------------------------------------------------------------
__global__ void select_kernel(const float* __restrict__ w,
                              const float* __restrict__ g) {
    float best = w[0] + g[0];
    int bi = 0;
    #pragma unroll
    for (int i = 1; i < 4; i++) {
        float v = w[i] + g[i];
        if (v > best) { best = v; bi = i; }
    }
    g_sel = bi;
}

// ------------------------------------------------------------------
// 1) input projections: GEMM (4104 x 384 x 384), BM=128 BN=128 BK=32
// ------------------------------------------------------------------
__global__ __launch_bounds__(256)
void proj_kernel(const float* __restrict__ x,
                 const float* Wq1, const float* bq1,
                 const float* Wq2, const float* bq2,
                 const float* Wk1, const float* bk1,
                 const float* Wk2, const float* bk2,
                 const float* Wv1, const float* bv1,
                 const float* Wv2, const float* bv2) {
    const int job = blockIdx.z;
    const int sel = g_sel;
    const float* W; const float* bias; float* OUT; int off;
    if (job == 0) { int qs = sel >> 1; W = qs ? Wq2 : Wq1; bias = qs ? bq2 : bq1; OUT = g_Q;  off = qs ? N1 : 0; }
    else if (job == 1) { int ks = sel & 1; W = ks ? Wk2 : Wk1; bias = ks ? bk2 : bk1; OUT = g_K;  off = ks ? N1 : 0; }
    else if (job == 2) { W = Wv1; bias = bv1; OUT = g_V1; off = 0;  }
    else               { W = Wv2; bias = bv2; OUT = g_V2; off = N1; }

    __shared__ float As[32][132];   // As[k][m]
    __shared__ float Bs[32][128];   // Bs[k][n]

    const int m0 = blockIdx.y * 128, n0 = blockIdx.x * 128;
    const int tid = threadIdx.x;
    const int ty = tid >> 4, tx = tid & 15;
    float acc[8][8];
    #pragma unroll
    for (int i = 0; i < 8; i++)
        #pragma unroll
        for (int j = 0; j < 8; j++) acc[i][j] = 0.f;

    for (int k0 = 0; k0 < CC; k0 += 32) {
        #pragma unroll
        for (int t = 0; t < 16; t++) {
            int idx = tid + t * 256;
            int mm = idx >> 5, kk = idx & 31;
            int m = m0 + mm;
            float v = 0.f;
            if (m < MROWS) {
                int b = m / N1, n = m % N1;
                v = x[((size_t)b * M_TOT + n + off) * CC + k0 + kk];
            }
            As[kk][mm] = v;
        }
        #pragma unroll
        for (int t = 0; t < 16; t++) {
            int idx = tid + t * 256;
            int kk = idx >> 7, nn = idx & 127;
            Bs[kk][nn] = W[(k0 + kk) * CC + n0 + nn];
        }
        __syncthreads();
        #pragma unroll
        for (int kk = 0; kk < 32; kk++) {
            float4 a0 = *(const float4*)&As[kk][ty * 8];
            float4 a1 = *(const float4*)&As[kk][ty * 8 + 4];
            float4 b0 = *(const float4*)&Bs[kk][tx * 8];
            float4 b1 = *(const float4*)&Bs[kk][tx * 8 + 4];
            const float a[8]  = {a0.x, a0.y, a0.z, a0.w, a1.x, a1.y, a1.z, a1.w};
            const float bb[8] = {b0.x, b0.y, b0.z, b0.w, b1.x, b1.y, b1.z, b1.w};
            #pragma unroll
            for (int i = 0; i < 8; i++)
                #pragma unroll
                for (int j = 0; j < 8; j++) acc[i][j] += a[i] * bb[j];
        }
        __syncthreads();
    }
    #pragma unroll
    for (int i = 0; i < 8; i++) {
        int m = m0 + ty * 8 + i;
        if (m >= MROWS) continue;
        float* dst = &OUT[(size_t)m * CC + n0 + tx * 8];
        const float* bp = &bias[n0 + tx * 8];
        float4 o0, o1;
        o0.x = acc[i][0] + bp[0]; o0.y = acc[i][1] + bp[1];
        o0.z = acc[i][2] + bp[2]; o0.w = acc[i][3] + bp[3];
        o1.x = acc[i][4] + bp[4]; o1.y = acc[i][5] + bp[5];
        o1.z = acc[i][6] + bp[6]; o1.w = acc[i][7] + bp[7];
        *(float4*)dst       = o0;
        *(float4*)(dst + 4) = o1;
    }
}

// ------------------------------------------------------------------
// 2) scores: S[bh][i][j] = scale * dot(Q[b,i,h,:], K[b,j,h,:])  (d=64)
// ------------------------------------------------------------------
__global__ __launch_bounds__(256)
void scores_kernel() {
    const int bh = blockIdx.z;
    const int b = bh / HH, hh = bh % HH;
    const int i0 = blockIdx.y * 64, j0 = blockIdx.x * 64;

    __shared__ float Qs[64][68];   // Qs[d][i]
    __shared__ float Ks[64][68];   // Ks[d][j]

    const int tid = threadIdx.x;
    const int ty = tid >> 4, tx = tid & 15;

    #pragma unroll
    for (int t = 0; t < 16; t++) {
        int idx = tid + t * 256;
        int r = idx >> 6, c = idx & 63;
        int qi = i0 + r;
        Qs[c][r] = (qi < N1) ? g_Q[((size_t)b * N1 + qi) * CC + hh * DD + c] : 0.f;
        int kj = j0 + r;
        Ks[c][r] = (kj < N1) ? g_K[((size_t)b * N1 + kj) * CC + hh * DD + c] : 0.f;
    }
    __syncthreads();

    float acc[4][4];
    #pragma unroll
    for (int i = 0; i < 4; i++)
        #pragma unroll
        for (int j = 0; j < 4; j++) acc[i][j] = 0.f;

    #pragma unroll
    for (int kk = 0; kk < 64; kk++) {
        float4 a  = *(const float4*)&Qs[kk][ty * 4];
        float4 bv = *(const float4*)&Ks[kk][tx * 4];
        const float av[4] = {a.x, a.y, a.z, a.w};
        const float bw[4] = {bv.x, bv.y, bv.z, bv.w};
        #pragma unroll
        for (int i = 0; i < 4; i++)
            #pragma unroll
            for (int j = 0; j < 4; j++) acc[i][j] += av[i] * bw[j];
    }

    const float scale = 0.125f;  // 64^-0.5
    const size_t base = (size_t)bh * N1 * N1;
    #pragma unroll
    for (int i = 0; i < 4; i++) {
        int qi = i0 + ty * 4 + i;
        if (qi >= N1) continue;
        #pragma unroll
        for (int j = 0; j < 4; j++) {
            int kj = j0 + tx * 4 + j;
            if (kj >= N1) continue;
            g_S[base + (size_t)qi * N1 + kj] = acc[i][j] * scale;
        }
    }
}

// ------------------------------------------------------------------
// 3) softmax: row cached in regs -> 1 read + 1 write of g_S.
//    Writes exp(s-m) in place, 1/sum to g_inv (normalization deferred).
// ------------------------------------------------------------------
__global__ __launch_bounds__(128)
void softmax_kernel() {
    const int row = blockIdx.x;
    float* p = g_S + (size_t)row * N1;
    const int t = threadIdx.x;
    __shared__ float redm[4];
    __shared__ float reds[4];

    float v[5];
    float m = -1e30f;
    #pragma unroll
    for (int c = 0; c < 5; c++) {
        int j = t + c * 128;
        v[c] = (j < N1) ? p[j] : -1e30f;
        m = fmaxf(m, v[c]);
    }
    #pragma unroll
    for (int o = 16; o > 0; o >>= 1) m = fmaxf(m, __shfl_xor_sync(0xffffffffu, m, o));
    if ((t & 31) == 0) redm[t >> 5] = m;
    __syncthreads();
    m = fmaxf(fmaxf(redm[0], redm[1]), fmaxf(redm[2], redm[3]));

    float s = 0.f;
    #pragma unroll
    for (int c = 0; c < 5; c++) {
        int j = t + c * 128;
        if (j < N1) {
            float e = __expf(v[c] - m);
            p[j] = e;
            s += e;
        }
    }
    #pragma unroll
    for (int o = 16; o > 0; o >>= 1) s += __shfl_xor_sync(0xffffffffu, s, o);
    if ((t & 31) == 0) reds[t >> 5] = s;
    __syncthreads();
    if (t == 0) g_inv[row] = 1.f / (reds[0] + reds[1] + reds[2] + reds[3]);
}

// ------------------------------------------------------------------
// 4) AV: per (bh, q-tile of 64): O = expS @ [V1|V2], * 1/sum at epilogue
//    128 threads, 8x8 accumulators, 26KB smem -> 4 CTAs/SM, grid fully
//    resident (432 <= 592)
// ------------------------------------------------------------------
__global__ __launch_bounds__(128, 4)
void av_kernel() {
    const int bh = blockIdx.y;
    const int b = bh / HH, hh = bh % HH;
    const int q0 = blockIdx.x * 64;

    __shared__ float As[32][68];    // As[k][q] (exp'd scores)
    __shared__ float Vs[32][132];   // Vs[k][j]  (j<64: V1, j>=64: V2)
    __shared__ float inv[64];

    const int tid = threadIdx.x;
    const int ty = tid >> 4, tx = tid & 15;     // ty 0..7 (8 q rows), tx 0..15 (8 cols)
    const size_t Sbase = (size_t)bh * N1 * N1;

    if (tid < 64) {
        int qi = q0 + tid;
        inv[tid] = (qi < N1) ? g_inv[bh * N1 + qi] : 0.f;
    }

    float acc[8][8];
    #pragma unroll
    for (int i = 0; i < 8; i++)
        #pragma unroll
        for (int j = 0; j < 8; j++) acc[i][j] = 0.f;

    for (int k0 = 0; k0 < 544; k0 += 32) {
        #pragma unroll
        for (int t = 0; t < 16; t++) {
            int idx = tid + t * 128;
            int q = idx >> 5, kk = idx & 31;
            int qi = q0 + q, ki = k0 + kk;
            As[kk][q] = (qi < N1 && ki < N1) ? g_S[Sbase + (size_t)qi * N1 + ki] : 0.f;
        }
        #pragma unroll
        for (int t = 0; t < 32; t++) {
            int idx = tid + t * 128;
            int kk = idx >> 7, j = idx & 127;
            int ki = k0 + kk;
            float v = 0.f;
            if (ki < N1) {
                if (j < 64) v = g_V1[((size_t)b * N1 + ki) * CC + hh * DD + j];
                else        v = g_V2[((size_t)b * N1 + ki) * CC + hh * DD + (j - 64)];
            }
            Vs[kk][j] = v;
        }
        __syncthreads();

        #pragma unroll
        for (int kk = 0; kk < 32; kk++) {
            float4 a0 = *(const float4*)&As[kk][ty * 8];
            float4 a1 = *(const float4*)&As[kk][ty * 8 + 4];
            float4 b0 = *(const float4*)&Vs[kk][tx * 8];
            float4 b1 = *(const float4*)&Vs[kk][tx * 8 + 4];
            const float a[8]  = {a0.x, a0.y, a0.z, a0.w, a1.x, a1.y, a1.z, a1.w};
            const float bw[8] = {b0.x, b0.y, b0.z, b0.w, b1.x, b1.y, b1.z, b1.w};
            #pragma unroll
            for (int i = 0; i < 8; i++)
                #pragma unroll
                for (int j = 0; j < 8; j++) acc[i][j] += a[i] * bw[j];
        }
        __syncthreads();
    }

    const int jj0 = tx * 8;
    const int c = hh * DD + (jj0 & 63);
    #pragma unroll
    for (int i = 0; i < 8; i++) {
        int q = ty * 8 + i;
        int qi = q0 + q;
        if (qi >= N1) continue;
        float sc = inv[q];
        int row = (jj0 < 64) ? qi : (N1 + qi);
        float4 o0, o1;
        o0.x = acc[i][0] * sc; o0.y = acc[i][1] * sc;
        o0.z = acc[i][2] * sc; o0.w = acc[i][3] * sc;
        o1.x = acc[i][4] * sc; o1.y = acc[i][5] * sc;
        o1.z = acc[i][6] * sc; o1.w = acc[i][7] * sc;
        float* dst = &g_O[((size_t)b * M_TOT + row) * CC + c];
        *(float4*)dst       = o0;
        *(float4*)(dst + 4) = o1;
    }
}

// ------------------------------------------------------------------
// 5) output projection: out = g_O (8208x384) @ Wo + bo
// ------------------------------------------------------------------
__global__ __launch_bounds__(256)
void final_kernel(const float* __restrict__ Wo,
                  const float* __restrict__ bo,
                  float* __restrict__ out) {
    __shared__ float As[32][132];
    __shared__ float Bs[32][128];

    const int m0 = blockIdx.y * 128, n0 = blockIdx.x * 128;
    const int tid = threadIdx.x;
    const int ty = tid >> 4, tx = tid & 15;
    float acc[8][8];
    #pragma unroll
    for (int i = 0; i < 8; i++)
        #pragma unroll
        for (int j = 0; j < 8; j++) acc[i][j] = 0.f;

    for (int k0 = 0; k0 < CC; k0 += 32) {
        #pragma unroll
        for (int t = 0; t < 16; t++) {
            int idx = tid + t * 256;
            int mm = idx >> 5, kk = idx & 31;
            int m = m0 + mm;
            As[kk][mm] = (m < MROWS2) ? g_O[(size_t)m * CC + k0 + kk] : 0.f;
        }
        #pragma unroll
        for (int t = 0; t < 16; t++) {
            int idx = tid + t * 256;
            int kk = idx >> 7, nn = idx & 127;
            Bs[kk][nn] = Wo[(k0 + kk) * CC + n0 + nn];
        }
        __syncthreads();
        #pragma unroll
        for (int kk = 0; kk < 32; kk++) {
            float4 a0 = *(const float4*)&As[kk][ty * 8];
            float4 a1 = *(const float4*)&As[kk][ty * 8 + 4];
            float4 b0 = *(const float4*)&Bs[kk][tx * 8];
            float4 b1 = *(const float4*)&Bs[kk][tx * 8 + 4];
            const float a[8]  = {a0.x, a0.y, a0.z, a0.w, a1.x, a1.y, a1.z, a1.w};
            const float bb[8] = {b0.x, b0.y, b0.z, b0.w, b1.x, b1.y, b1.z, b1.w};
            #pragma unroll
            for (int i = 0; i < 8; i++)
                #pragma unroll
                for (int j = 0; j < 8; j++) acc[i][j] += a[i] * bb[j];
        }
        __syncthreads();
    }
    #pragma unroll
    for (int i = 0; i < 8; i++) {
        int m = m0 + ty * 8 + i;
        if (m >= MROWS2) continue;
        float* dst = &out[(size_t)m * CC + n0 + tx * 8];
        const float* bp = &bo[n0 + tx * 8];
        float4 o0, o1;
        o0.x = acc[i][0] + bp[0]; o0.y = acc[i][1] + bp[1];
        o0.z = acc[i][2] + bp[2]; o0.w = acc[i][3] + bp[3];
        o1.x = acc[i][4] + bp[4]; o1.y = acc[i][5] + bp[5];
        o1.z = acc[i][6] + bp[6]; o1.w = acc[i][7] + bp[7];
        *(float4*)dst       = o0;
        *(float4*)(dst + 4) = o1;
    }
}

// ------------------------------------------------------------------
extern "C" void kernel_launch(void* const* d_in, const int* in_sizes, int n_in,
                              void* d_out, int out_size) {
    const float* x   = (const float*)d_in[0];
    const float* Wq1 = (const float*)d_in[1];  const float* bq1 = (const float*)d_in[2];
    const float* Wq2 = (const float*)d_in[3];  const float* bq2 = (const float*)d_in[4];
    const float* Wk1 = (const float*)d_in[5];  const float* bk1 = (const float*)d_in[6];
    const float* Wk2 = (const float*)d_in[7];  const float* bk2 = (const float*)d_in[8];
    const float* Wv1 = (const float*)d_in[9];  const float* bv1 = (const float*)d_in[10];
    const float* Wv2 = (const float*)d_in[11]; const float* bv2 = (const float*)d_in[12];
    const float* Wo  = (const float*)d_in[13]; const float* bo  = (const float*)d_in[14];
    const float* wts = (const float*)d_in[15]; const float* gum = (const float*)d_in[16];
    float* out = (float*)d_out;

    select_kernel<<<1, 1>>>(wts, gum);

    dim3 pg(CC / 128, (MROWS + 127) / 128, 4);              // 3 x 33 x 4
    proj_kernel<<<pg, 256>>>(x, Wq1, bq1, Wq2, bq2, Wk1, bk1, Wk2, bk2,
                             Wv1, bv1, Wv2, bv2);

    dim3 sg((N1 + 63) / 64, (N1 + 63) / 64, BHN);           // 9 x 9 x 48
    scores_kernel<<<sg, 256>>>();

    softmax_kernel<<<BHN * N1, 128>>>();

    av_kernel<<<dim3((N1 + 63) / 64, BHN), 128>>>();        // 9 x 48

    final_kernel<<<dim3(CC / 128, (MROWS2 + 127) / 128, 1), 256>>>(Wo, bo, out);
}

// round 7
// speedup vs baseline: 1.2937x; 1.1107x over previous
#include <cuda_runtime.h>
#include <math.h>

#define BB     8
#define M_TOT  1026
#define CC     384
#define N1     513
#define HH     6
#define DD     64
#define BHN    (BB*HH)      // 48
#define MROWS  (BB*N1)      // 4104
#define MROWS2 (BB*M_TOT)   // 8208

// ---- scratch (device globals; no cudaMalloc allowed) ----
__device__ int   g_sel;
__device__ float g_Q [MROWS*CC];
__device__ float g_K [MROWS*CC];
__device__ float g_V1[MROWS*CC];
__device__ float g_V2[MROWS*CC];
__device__ float g_S [(size_t)BHN*N1*N1];   // scores -> exp'd scores (~50.5MB, L2)
__device__ float g_inv[BHN*N1];             // 1/rowsum
__device__ float g_O [MROWS2*CC];           // pre-Wo activations

// ------------------------------------------------------------------
// 0) straight-through gumbel selection: argmax(weights + noise)
// ------------------------------------------------------------------
__global__ void select_kernel(const float* __restrict__ w,
                              const float* __restrict__ g) {
    float best = w[0] + g[0];
    int bi = 0;
    #pragma unroll
    for (int i = 1; i < 4; i++) {
        float v = w[i] + g[i];
        if (v > best) { best = v; bi = i; }
    }
    g_sel = bi;
}

// ------------------------------------------------------------------
// 1) input projections: GEMM (4104 x 384 x 384), BM=128 BN=128 BK=32
// ------------------------------------------------------------------
__global__ __launch_bounds__(256)
void proj_kernel(const float* __restrict__ x,
                 const float* Wq1, const float* bq1,
                 const float* Wq2, const float* bq2,
                 const float* Wk1, const float* bk1,
                 const float* Wk2, const float* bk2,
                 const float* Wv1, const float* bv1,
                 const float* Wv2, const float* bv2) {
    const int job = blockIdx.z;
    const int sel = g_sel;
    const float* W; const float* bias; float* OUT; int off;
    if (job == 0) { int qs = sel >> 1; W = qs ? Wq2 : Wq1; bias = qs ? bq2 : bq1; OUT = g_Q;  off = qs ? N1 : 0; }
    else if (job == 1) { int ks = sel & 1; W = ks ? Wk2 : Wk1; bias = ks ? bk2 : bk1; OUT = g_K;  off = ks ? N1 : 0; }
    else if (job == 2) { W = Wv1; bias = bv1; OUT = g_V1; off = 0;  }
    else               { W = Wv2; bias = bv2; OUT = g_V2; off = N1; }

    __shared__ float As[32][132];   // As[k][m]
    __shared__ float Bs[32][128];   // Bs[k][n]

    const int m0 = blockIdx.y * 128, n0 = blockIdx.x * 128;
    const int tid = threadIdx.x;
    const int ty = tid >> 4, tx = tid & 15;
    float acc[8][8];
    #pragma unroll
    for (int i = 0; i < 8; i++)
        #pragma unroll
        for (int j = 0; j < 8; j++) acc[i][j] = 0.f;

    for (int k0 = 0; k0 < CC; k0 += 32) {
        #pragma unroll
        for (int t = 0; t < 16; t++) {
            int idx = tid + t * 256;
            int mm = idx >> 5, kk = idx & 31;
            int m = m0 + mm;
            float v = 0.f;
            if (m < MROWS) {
                int b = m / N1, n = m % N1;
                v = x[((size_t)b * M_TOT + n + off) * CC + k0 + kk];
            }
            As[kk][mm] = v;
        }
        #pragma unroll
        for (int t = 0; t < 16; t++) {
            int idx = tid + t * 256;
            int kk = idx >> 7, nn = idx & 127;
            Bs[kk][nn] = W[(k0 + kk) * CC + n0 + nn];
        }
        __syncthreads();
        #pragma unroll
        for (int kk = 0; kk < 32; kk++) {
            float4 a0 = *(const float4*)&As[kk][ty * 8];
            float4 a1 = *(const float4*)&As[kk][ty * 8 + 4];
            float4 b0 = *(const float4*)&Bs[kk][tx * 8];
            float4 b1 = *(const float4*)&Bs[kk][tx * 8 + 4];
            const float a[8]  = {a0.x, a0.y, a0.z, a0.w, a1.x, a1.y, a1.z, a1.w};
            const float bb[8] = {b0.x, b0.y, b0.z, b0.w, b1.x, b1.y, b1.z, b1.w};
            #pragma unroll
            for (int i = 0; i < 8; i++)
                #pragma unroll
                for (int j = 0; j < 8; j++) acc[i][j] += a[i] * bb[j];
        }
        __syncthreads();
    }
    #pragma unroll
    for (int i = 0; i < 8; i++) {
        int m = m0 + ty * 8 + i;
        if (m >= MROWS) continue;
        float* dst = &OUT[(size_t)m * CC + n0 + tx * 8];
        const float* bp = &bias[n0 + tx * 8];
        float4 o0, o1;
        o0.x = acc[i][0] + bp[0]; o0.y = acc[i][1] + bp[1];
        o0.z = acc[i][2] + bp[2]; o0.w = acc[i][3] + bp[3];
        o1.x = acc[i][4] + bp[4]; o1.y = acc[i][5] + bp[5];
        o1.z = acc[i][6] + bp[6]; o1.w = acc[i][7] + bp[7];
        *(float4*)dst       = o0;
        *(float4*)(dst + 4) = o1;
    }
}

// ------------------------------------------------------------------
// 2) scores: S[bh][i][j] = scale * dot(Q[b,i,h,:], K[b,j,h,:])  (d=64)
// ------------------------------------------------------------------
__global__ __launch_bounds__(256)
void scores_kernel() {
    const int bh = blockIdx.z;
    const int b = bh / HH, hh = bh % HH;
    const int i0 = blockIdx.y * 64, j0 = blockIdx.x * 64;

    __shared__ float Qs[64][68];   // Qs[d][i]
    __shared__ float Ks[64][68];   // Ks[d][j]

    const int tid = threadIdx.x;
    const int ty = tid >> 4, tx = tid & 15;

    #pragma unroll
    for (int t = 0; t < 16; t++) {
        int idx = tid + t * 256;
        int r = idx >> 6, c = idx & 63;
        int qi = i0 + r;
        Qs[c][r] = (qi < N1) ? g_Q[((size_t)b * N1 + qi) * CC + hh * DD + c] : 0.f;
        int kj = j0 + r;
        Ks[c][r] = (kj < N1) ? g_K[((size_t)b * N1 + kj) * CC + hh * DD + c] : 0.f;
    }
    __syncthreads();

    float acc[4][4];
    #pragma unroll
    for (int i = 0; i < 4; i++)
        #pragma unroll
        for (int j = 0; j < 4; j++) acc[i][j] = 0.f;

    #pragma unroll
    for (int kk = 0; kk < 64; kk++) {
        float4 a  = *(const float4*)&Qs[kk][ty * 4];
        float4 bv = *(const float4*)&Ks[kk][tx * 4];
        const float av[4] = {a.x, a.y, a.z, a.w};
        const float bw[4] = {bv.x, bv.y, bv.z, bv.w};
        #pragma unroll
        for (int i = 0; i < 4; i++)
            #pragma unroll
            for (int j = 0; j < 4; j++) acc[i][j] += av[i] * bw[j];
    }

    const float scale = 0.125f;  // 64^-0.5
    const size_t base = (size_t)bh * N1 * N1;
    #pragma unroll
    for (int i = 0; i < 4; i++) {
        int qi = i0 + ty * 4 + i;
        if (qi >= N1) continue;
        #pragma unroll
        for (int j = 0; j < 4; j++) {
            int kj = j0 + tx * 4 + j;
            if (kj >= N1) continue;
            g_S[base + (size_t)qi * N1 + kj] = acc[i][j] * scale;
        }
    }
}

// ------------------------------------------------------------------
// 3) softmax: row cached in regs -> 1 read + 1 write of g_S.
//    Writes exp(s-m) in place, 1/sum to g_inv (normalization deferred).
// ------------------------------------------------------------------
__global__ __launch_bounds__(128)
void softmax_kernel() {
    const int row = blockIdx.x;
    float* p = g_S + (size_t)row * N1;
    const int t = threadIdx.x;
    __shared__ float redm[4];
    __shared__ float reds[4];

    float v[5];
    float m = -1e30f;
    #pragma unroll
    for (int c = 0; c < 5; c++) {
        int j = t + c * 128;
        v[c] = (j < N1) ? p[j] : -1e30f;
        m = fmaxf(m, v[c]);
    }
    #pragma unroll
    for (int o = 16; o > 0; o >>= 1) m = fmaxf(m, __shfl_xor_sync(0xffffffffu, m, o));
    if ((t & 31) == 0) redm[t >> 5] = m;
    __syncthreads();
    m = fmaxf(fmaxf(redm[0], redm[1]), fmaxf(redm[2], redm[3]));

    float s = 0.f;
    #pragma unroll
    for (int c = 0; c < 5; c++) {
        int j = t + c * 128;
        if (j < N1) {
            float e = __expf(v[c] - m);
            p[j] = e;
            s += e;
        }
    }
    #pragma unroll
    for (int o = 16; o > 0; o >>= 1) s += __shfl_xor_sync(0xffffffffu, s, o);
    if ((t & 31) == 0) reds[t >> 5] = s;
    __syncthreads();
    if (t == 0) g_inv[row] = 1.f / (reds[0] + reds[1] + reds[2] + reds[3]);
}

// ------------------------------------------------------------------
// 4) AV: O = expS @ [V1|V2], * 1/sum at epilogue.
//    Proj-identical structure: 256 thr, BM=128 BN=128 BK=32, 8x8 acc.
//    grid 5 x 48 = 240 CTAs, single wave.
// ------------------------------------------------------------------
__global__ __launch_bounds__(256)
void av_kernel() {
    const int bh = blockIdx.y;
    const int b = bh / HH, hh = bh % HH;
    const int q0 = blockIdx.x * 128;

    __shared__ float As[32][132];   // As[k][q] (exp'd scores, transposed)
    __shared__ float Vs[32][132];   // Vs[k][j]  (j<64: V1, j>=64: V2)

    const int tid = threadIdx.x;
    const int ty = tid >> 4, tx = tid & 15;
    const size_t Sbase = (size_t)bh * N1 * N1;

    float acc[8][8];
    #pragma unroll
    for (int i = 0; i < 8; i++)
        #pragma unroll
        for (int j = 0; j < 8; j++) acc[i][j] = 0.f;

    for (int k0 = 0; k0 < 544; k0 += 32) {
        #pragma unroll
        for (int t = 0; t < 16; t++) {
            int idx = tid + t * 256;
            int q = idx >> 5, kk = idx & 31;
            int qi = q0 + q, ki = k0 + kk;
            As[kk][q] = (qi < N1 && ki < N1) ? g_S[Sbase + (size_t)qi * N1 + ki] : 0.f;
        }
        #pragma unroll
        for (int t = 0; t < 16; t++) {
            int idx = tid + t * 256;
            int kk = idx >> 7, j = idx & 127;
            int ki = k0 + kk;
            float v = 0.f;
            if (ki < N1) {
                if (j < 64) v = g_V1[((size_t)b * N1 + ki) * CC + hh * DD + j];
                else        v = g_V2[((size_t)b * N1 + ki) * CC + hh * DD + (j - 64)];
            }
            Vs[kk][j] = v;
        }
        __syncthreads();

        #pragma unroll
        for (int kk = 0; kk < 32; kk++) {
            float4 a0 = *(const float4*)&As[kk][ty * 8];
            float4 a1 = *(const float4*)&As[kk][ty * 8 + 4];
            float4 b0 = *(const float4*)&Vs[kk][tx * 8];
            float4 b1 = *(const float4*)&Vs[kk][tx * 8 + 4];
            const float a[8]  = {a0.x, a0.y, a0.z, a0.w, a1.x, a1.y, a1.z, a1.w};
            const float bw[8] = {b0.x, b0.y, b0.z, b0.w, b1.x, b1.y, b1.z, b1.w};
            #pragma unroll
            for (int i = 0; i < 8; i++)
                #pragma unroll
                for (int j = 0; j < 8; j++) acc[i][j] += a[i] * bw[j];
        }
        __syncthreads();
    }

    const int jj0 = tx * 8;
    const int c = hh * DD + (jj0 & 63);
    #pragma unroll
    for (int i = 0; i < 8; i++) {
        int qi = q0 + ty * 8 + i;
        if (qi >= N1) continue;
        float sc = g_inv[bh * N1 + qi];
        int row = (jj0 < 64) ? qi : (N1 + qi);
        float4 o0, o1;
        o0.x = acc[i][0] * sc; o0.y = acc[i][1] * sc;
        o0.z = acc[i][2] * sc; o0.w = acc[i][3] * sc;
        o1.x = acc[i][4] * sc; o1.y = acc[i][5] * sc;
        o1.z = acc[i][6] * sc; o1.w = acc[i][7] * sc;
        float* dst = &g_O[((size_t)b * M_TOT + row) * CC + c];
        *(float4*)dst       = o0;
        *(float4*)(dst + 4) = o1;
    }
}

// ------------------------------------------------------------------
// 5) output projection: out = g_O (8208x384) @ Wo + bo
// ------------------------------------------------------------------
__global__ __launch_bounds__(256)
void final_kernel(const float* __restrict__ Wo,
                  const float* __restrict__ bo,
                  float* __restrict__ out) {
    __shared__ float As[32][132];
    __shared__ float Bs[32][128];

    const int m0 = blockIdx.y * 128, n0 = blockIdx.x * 128;
    const int tid = threadIdx.x;
    const int ty = tid >> 4, tx = tid & 15;
    float acc[8][8];
    #pragma unroll
    for (int i = 0; i < 8; i++)
        #pragma unroll
        for (int j = 0; j < 8; j++) acc[i][j] = 0.f;

    for (int k0 = 0; k0 < CC; k0 += 32) {
        #pragma unroll
        for (int t = 0; t < 16; t++) {
            int idx = tid + t * 256;
            int mm = idx >> 5, kk = idx & 31;
            int m = m0 + mm;
            As[kk][mm] = (m < MROWS2) ? g_O[(size_t)m * CC + k0 + kk] : 0.f;
        }
        #pragma unroll
        for (int t = 0; t < 16; t++) {
            int idx = tid + t * 256;
            int kk = idx >> 7, nn = idx & 127;
            Bs[kk][nn] = Wo[(k0 + kk) * CC + n0 + nn];
        }
        __syncthreads();
        #pragma unroll
        for (int kk = 0; kk < 32; kk++) {
            float4 a0 = *(const float4*)&As[kk][ty * 8];
            float4 a1 = *(const float4*)&As[kk][ty * 8 + 4];
            float4 b0 = *(const float4*)&Bs[kk][tx * 8];
            float4 b1 = *(const float4*)&Bs[kk][tx * 8 + 4];
            const float a[8]  = {a0.x, a0.y, a0.z, a0.w, a1.x, a1.y, a1.z, a1.w};
            const float bb[8] = {b0.x, b0.y, b0.z, b0.w, b1.x, b1.y, b1.z, b1.w};
            #pragma unroll
            for (int i = 0; i < 8; i++)
                #pragma unroll
                for (int j = 0; j < 8; j++) acc[i][j] += a[i] * bb[j];
        }
        __syncthreads();
    }
    #pragma unroll
    for (int i = 0; i < 8; i++) {
        int m = m0 + ty * 8 + i;
        if (m >= MROWS2) continue;
        float* dst = &out[(size_t)m * CC + n0 + tx * 8];
        const float* bp = &bo[n0 + tx * 8];
        float4 o0, o1;
        o0.x = acc[i][0] + bp[0]; o0.y = acc[i][1] + bp[1];
        o0.z = acc[i][2] + bp[2]; o0.w = acc[i][3] + bp[3];
        o1.x = acc[i][4] + bp[4]; o1.y = acc[i][5] + bp[5];
        o1.z = acc[i][6] + bp[6]; o1.w = acc[i][7] + bp[7];
        *(float4*)dst       = o0;
        *(float4*)(dst + 4) = o1;
    }
}

// ------------------------------------------------------------------
extern "C" void kernel_launch(void* const* d_in, const int* in_sizes, int n_in,
                              void* d_out, int out_size) {
    const float* x   = (const float*)d_in[0];
    const float* Wq1 = (const float*)d_in[1];  const float* bq1 = (const float*)d_in[2];
    const float* Wq2 = (const float*)d_in[3];  const float* bq2 = (const float*)d_in[4];
    const float* Wk1 = (const float*)d_in[5];  const float* bk1 = (const float*)d_in[6];
    const float* Wk2 = (const float*)d_in[7];  const float* bk2 = (const float*)d_in[8];
    const float* Wv1 = (const float*)d_in[9];  const float* bv1 = (const float*)d_in[10];
    const float* Wv2 = (const float*)d_in[11]; const float* bv2 = (const float*)d_in[12];
    const float* Wo  = (const float*)d_in[13]; const float* bo  = (const float*)d_in[14];
    const float* wts = (const float*)d_in[15]; const float* gum = (const float*)d_in[16];
    float* out = (float*)d_out;

    select_kernel<<<1, 1>>>(wts, gum);

    dim3 pg(CC / 128, (MROWS + 127) / 128, 4);              // 3 x 33 x 4
    proj_kernel<<<pg, 256>>>(x, Wq1, bq1, Wq2, bq2, Wk1, bk1, Wk2, bk2,
                             Wv1, bv1, Wv2, bv2);

    dim3 sg((N1 + 63) / 64, (N1 + 63) / 64, BHN);           // 9 x 9 x 48
    scores_kernel<<<sg, 256>>>();

    softmax_kernel<<<BHN * N1, 128>>>();

    av_kernel<<<dim3((N1 + 127) / 128, BHN), 256>>>();      // 5 x 48

    final_kernel<<<dim3(CC / 128, (MROWS2 + 127) / 128, 1), 256>>>(Wo, bo, out);
}

// round 9
// speedup vs baseline: 1.5636x; 1.2086x over previous
#include <cuda_runtime.h>
#include <cuda_bf16.h>
#include <stdint.h>
#include <math.h>

#define BB     8
#define M_TOT  1026
#define CC     384
#define N1     513
#define HH     6
#define DD     64
#define BHN    (BB*HH)      // 48
#define MROWS  (BB*N1)      // 4104
#define MROWS2 (BB*M_TOT)   // 8208

// ---- scratch (device globals; no cudaMalloc allowed) ----
__device__ int   g_sel;
__device__ float g_Q [MROWS*CC];
__device__ float g_K [MROWS*CC];
__device__ float g_V1[MROWS*CC];
__device__ float g_V2[MROWS*CC];
__device__ float g_S [(size_t)BHN*N1*N1];   // scores -> exp'd scores (~50.5MB, L2)
__device__ float g_inv[BHN*N1];             // 1/rowsum
__device__ float g_O [MROWS2*CC];           // pre-Wo activations

// ------------------------------------------------------------------
// 0) straight-through gumbel selection: argmax(weights + noise)
// ------------------------------------------------------------------
__global__ void select_kernel(const float* __restrict__ w,
                              const float* __restrict__ g) {
    float best = w[0] + g[0];
    int bi = 0;
    #pragma unroll
    for (int i = 1; i < 4; i++) {
        float v = w[i] + g[i];
        if (v > best) { best = v; bi = i; }
    }
    g_sel = bi;
}

// ==================================================================
// bf16 3-pass (hi/lo split) tensor-core GEMM pieces
//   C[M,384] = A[M,384] @ W[384,384] + bias
//   BM=128 BN=128 BK=32, 256 threads (8 warps = 2m x 4n), warp=64x32
//   smem: Ah/Al bf16[128][34]  (row-major [m][k], k-pairs packed)
//         Bh/Bl bf16[128][34]  (transposed  [n][k], k-pairs packed)
// ==================================================================
#define KST 34          // bf16 row stride (17 u32)
#define KSTU 17         // u32 row stride

__device__ __forceinline__ void bf16_split2(float2 f, __nv_bfloat162* hi, __nv_bfloat162* lo) {
    __nv_bfloat16 hx = __float2bfloat16(f.x);
    __nv_bfloat16 hy = __float2bfloat16(f.y);
    __nv_bfloat16 lx = __float2bfloat16(f.x - __bfloat162float(hx));
    __nv_bfloat16 ly = __float2bfloat16(f.y - __bfloat162float(hy));
    hi->x = hx; hi->y = hy;
    lo->x = lx; lo->y = ly;
}

__device__ __forceinline__ void mma_bf16(float* d, uint32_t a0, uint32_t a1,
                                         uint32_t a2, uint32_t a3,
                                         uint32_t b0, uint32_t b1) {
    asm volatile(
        "mma.sync.aligned.m16n8k16.row.col.f32.bf16.bf16.f32 "
        "{%0,%1,%2,%3},{%4,%5,%6,%7},{%8,%9},{%0,%1,%2,%3};"
        : "+f"(d[0]), "+f"(d[1]), "+f"(d[2]), "+f"(d[3])
        : "r"(a0), "r"(a1), "r"(a2), "r"(a3), "r"(b0), "r"(b1));
}

// ------------------------------------------------------------------
// 1) input projections via bf16 mma: 4 jobs, grid (3, 33, 4)
// ------------------------------------------------------------------
__global__ __launch_bounds__(256)
void proj_kernel(const float* __restrict__ x,
                 const float* Wq1, const float* bq1,
                 const float* Wq2, const float* bq2,
                 const float* Wk1, const float* bk1,
                 const float* Wk2, const float* bk2,
                 const float* Wv1, const float* bv1,
                 const float* Wv2, const float* bv2) {
    const int job = blockIdx.z;
    const int sel = g_sel;
    const float* W; const float* bias; float* OUT; int off;
    if (job == 0) { int qs = sel >> 1; W = qs ? Wq2 : Wq1; bias = qs ? bq2 : bq1; OUT = g_Q;  off = qs ? N1 : 0; }
    else if (job == 1) { int ks = sel & 1; W = ks ? Wk2 : Wk1; bias = ks ? bk2 : bk1; OUT = g_K;  off = ks ? N1 : 0; }
    else if (job == 2) { W = Wv1; bias = bv1; OUT = g_V1; off = 0;  }
    else               { W = Wv2; bias = bv2; OUT = g_V2; off = N1; }

    __shared__ __nv_bfloat16 Ah[128][KST], Al[128][KST];
    __shared__ __nv_bfloat16 Bh[128][KST], Bl[128][KST];

    const int m0 = blockIdx.y * 128, n0 = blockIdx.x * 128;
    const int tid  = threadIdx.x;
    const int warp = tid >> 5, lane = tid & 31;
    const int wm = warp >> 2, wn = warp & 3;           // 2 x 4
    const int g = lane >> 2, t = lane & 3;

    float d[4][4][4];                                   // [mt][nt][frag]
    #pragma unroll
    for (int i = 0; i < 4; i++)
        #pragma unroll
        for (int j = 0; j < 4; j++)
            #pragma unroll
            for (int r = 0; r < 4; r++) d[i][j][r] = 0.f;

    const uint32_t* Ah32 = (const uint32_t*)&Ah[0][0];
    const uint32_t* Al32 = (const uint32_t*)&Al[0][0];
    const uint32_t* Bh32 = (const uint32_t*)&Bh[0][0];
    const uint32_t* Bl32 = (const uint32_t*)&Bl[0][0];

    for (int k0 = 0; k0 < CC; k0 += 32) {
        // ---- stage A: 128 rows x 16 k-pairs ----
        #pragma unroll
        for (int it = 0; it < 8; it++) {
            int slot = tid + it * 256;
            int ml = slot >> 4, kp = slot & 15;
            int m = m0 + ml;
            float2 f = make_float2(0.f, 0.f);
            if (m < MROWS) {
                int b = m / N1, n = m % N1;
                f = *(const float2*)&x[((size_t)b * M_TOT + n + off) * CC + k0 + 2 * kp];
            }
            __nv_bfloat162 hi, lo;
            bf16_split2(f, &hi, &lo);
            *(__nv_bfloat162*)&Ah[ml][2 * kp] = hi;
            *(__nv_bfloat162*)&Al[ml][2 * kp] = lo;
        }
        // ---- stage B transposed: [n][k] ----
        #pragma unroll
        for (int it = 0; it < 8; it++) {
            int slot = tid + it * 256;
            int nl = slot & 127, kp = slot >> 7;
            float2 f;
            f.x = W[(size_t)(k0 + 2 * kp)     * CC + n0 + nl];
            f.y = W[(size_t)(k0 + 2 * kp + 1) * CC + n0 + nl];
            __nv_bfloat162 hi, lo;
            bf16_split2(f, &hi, &lo);
            *(__nv_bfloat162*)&Bh[nl][2 * kp] = hi;
            *(__nv_bfloat162*)&Bl[nl][2 * kp] = lo;
        }
        __syncthreads();

        #pragma unroll
        for (int ks = 0; ks < 2; ks++) {
            const int ko = ks * 8;
            uint32_t bh[4][2], bl[4][2];
            #pragma unroll
            for (int nt = 0; nt < 4; nt++) {
                int nb = (wn * 32 + nt * 8 + g) * KSTU + ko + t;
                bh[nt][0] = Bh32[nb];     bh[nt][1] = Bh32[nb + 4];
                bl[nt][0] = Bl32[nb];     bl[nt][1] = Bl32[nb + 4];
            }
            #pragma unroll
            for (int mt = 0; mt < 4; mt++) {
                int ab = (wm * 64 + mt * 16 + g) * KSTU + ko + t;
                uint32_t ah0 = Ah32[ab],            ah1 = Ah32[ab + 8 * KSTU];
                uint32_t ah2 = Ah32[ab + 4],        ah3 = Ah32[ab + 4 + 8 * KSTU];
                uint32_t al0 = Al32[ab],            al1 = Al32[ab + 8 * KSTU];
                uint32_t al2 = Al32[ab + 4],        al3 = Al32[ab + 4 + 8 * KSTU];
                #pragma unroll
                for (int nt = 0; nt < 4; nt++) {
                    mma_bf16(d[mt][nt], ah0, ah1, ah2, ah3, bh[nt][0], bh[nt][1]);
                    mma_bf16(d[mt][nt], ah0, ah1, ah2, ah3, bl[nt][0], bl[nt][1]);
                    mma_bf16(d[mt][nt], al0, al1, al2, al3, bh[nt][0], bh[nt][1]);
                }
            }
        }
        __syncthreads();
    }

    // ---- epilogue ----
    #pragma unroll
    for (int mt = 0; mt < 4; mt++) {
        #pragma unroll
        for (int nt = 0; nt < 4; nt++) {
            int m = m0 + wm * 64 + mt * 16 + g;
            int c = n0 + wn * 32 + nt * 8 + 2 * t;
            float b0v = bias[c], b1v = bias[c + 1];
            if (m < MROWS) {
                float2 o; o.x = d[mt][nt][0] + b0v; o.y = d[mt][nt][1] + b1v;
                *(float2*)&OUT[(size_t)m * CC + c] = o;
            }
            if (m + 8 < MROWS) {
                float2 o; o.x = d[mt][nt][2] + b0v; o.y = d[mt][nt][3] + b1v;
                *(float2*)&OUT[(size_t)(m + 8) * CC + c] = o;
            }
        }
    }
}

// ------------------------------------------------------------------
// 2) scores: S[bh][i][j] = scale * dot(Q[b,i,h,:], K[b,j,h,:])  (d=64)
// ------------------------------------------------------------------
__global__ __launch_bounds__(256)
void scores_kernel() {
    const int bh = blockIdx.z;
    const int b = bh / HH, hh = bh % HH;
    const int i0 = blockIdx.y * 64, j0 = blockIdx.x * 64;

    __shared__ float Qs[64][68];   // Qs[d][i]
    __shared__ float Ks[64][68];   // Ks[d][j]

    const int tid = threadIdx.x;
    const int ty = tid >> 4, tx = tid & 15;

    #pragma unroll
    for (int t = 0; t < 16; t++) {
        int idx = tid + t * 256;
        int r = idx >> 6, c = idx & 63;
        int qi = i0 + r;
        Qs[c][r] = (qi < N1) ? g_Q[((size_t)b * N1 + qi) * CC + hh * DD + c] : 0.f;
        int kj = j0 + r;
        Ks[c][r] = (kj < N1) ? g_K[((size_t)b * N1 + kj) * CC + hh * DD + c] : 0.f;
    }
    __syncthreads();

    float acc[4][4];
    #pragma unroll
    for (int i = 0; i < 4; i++)
        #pragma unroll
        for (int j = 0; j < 4; j++) acc[i][j] = 0.f;

    #pragma unroll
    for (int kk = 0; kk < 64; kk++) {
        float4 a  = *(const float4*)&Qs[kk][ty * 4];
        float4 bv = *(const float4*)&Ks[kk][tx * 4];
        const float av[4] = {a.x, a.y, a.z, a.w};
        const float bw[4] = {bv.x, bv.y, bv.z, bv.w};
        #pragma unroll
        for (int i = 0; i < 4; i++)
            #pragma unroll
            for (int j = 0; j < 4; j++) acc[i][j] += av[i] * bw[j];
    }

    const float scale = 0.125f;  // 64^-0.5
    const size_t base = (size_t)bh * N1 * N1;
    #pragma unroll
    for (int i = 0; i < 4; i++) {
        int qi = i0 + ty * 4 + i;
        if (qi >= N1) continue;
        #pragma unroll
        for (int j = 0; j < 4; j++) {
            int kj = j0 + tx * 4 + j;
            if (kj >= N1) continue;
            g_S[base + (size_t)qi * N1 + kj] = acc[i][j] * scale;
        }
    }
}

// ------------------------------------------------------------------
// 3) softmax: row cached in regs -> 1 read + 1 write of g_S.
// ------------------------------------------------------------------
__global__ __launch_bounds__(128)
void softmax_kernel() {
    const int row = blockIdx.x;
    float* p = g_S + (size_t)row * N1;
    const int t = threadIdx.x;
    __shared__ float redm[4];
    __shared__ float reds[4];

    float v[5];
    float m = -1e30f;
    #pragma unroll
    for (int c = 0; c < 5; c++) {
        int j = t + c * 128;
        v[c] = (j < N1) ? p[j] : -1e30f;
        m = fmaxf(m, v[c]);
    }
    #pragma unroll
    for (int o = 16; o > 0; o >>= 1) m = fmaxf(m, __shfl_xor_sync(0xffffffffu, m, o));
    if ((t & 31) == 0) redm[t >> 5] = m;
    __syncthreads();
    m = fmaxf(fmaxf(redm[0], redm[1]), fmaxf(redm[2], redm[3]));

    float s = 0.f;
    #pragma unroll
    for (int c = 0; c < 5; c++) {
        int j = t + c * 128;
        if (j < N1) {
            float e = __expf(v[c] - m);
            p[j] = e;
            s += e;
        }
    }
    #pragma unroll
    for (int o = 16; o > 0; o >>= 1) s += __shfl_xor_sync(0xffffffffu, s, o);
    if ((t & 31) == 0) reds[t >> 5] = s;
    __syncthreads();
    if (t == 0) g_inv[row] = 1.f / (reds[0] + reds[1] + reds[2] + reds[3]);
}

// ------------------------------------------------------------------
// 4) AV: O = expS @ [V1|V2], * 1/sum at epilogue (fp32 SIMT, R7 form)
// ------------------------------------------------------------------
__global__ __launch_bounds__(256)
void av_kernel() {
    const int bh = blockIdx.y;
    const int b = bh / HH, hh = bh % HH;
    const int q0 = blockIdx.x * 128;

    __shared__ float As[32][132];   // As[k][q] (exp'd scores, transposed)
    __shared__ float Vs[32][132];   // Vs[k][j]  (j<64: V1, j>=64: V2)

    const int tid = threadIdx.x;
    const int ty = tid >> 4, tx = tid & 15;
    const size_t Sbase = (size_t)bh * N1 * N1;

    float acc[8][8];
    #pragma unroll
    for (int i = 0; i < 8; i++)
        #pragma unroll
        for (int j = 0; j < 8; j++) acc[i][j] = 0.f;

    for (int k0 = 0; k0 < 544; k0 += 32) {
        #pragma unroll
        for (int t = 0; t < 16; t++) {
            int idx = tid + t * 256;
            int q = idx >> 5, kk = idx & 31;
            int qi = q0 + q, ki = k0 + kk;
            As[kk][q] = (qi < N1 && ki < N1) ? g_S[Sbase + (size_t)qi * N1 + ki] : 0.f;
        }
        #pragma unroll
        for (int t = 0; t < 16; t++) {
            int idx = tid + t * 256;
            int kk = idx >> 7, j = idx & 127;
            int ki = k0 + kk;
            float v = 0.f;
            if (ki < N1) {
                if (j < 64) v = g_V1[((size_t)b * N1 + ki) * CC + hh * DD + j];
                else        v = g_V2[((size_t)b * N1 + ki) * CC + hh * DD + (j - 64)];
            }
            Vs[kk][j] = v;
        }
        __syncthreads();

        #pragma unroll
        for (int kk = 0; kk < 32; kk++) {
            float4 a0 = *(const float4*)&As[kk][ty * 8];
            float4 a1 = *(const float4*)&As[kk][ty * 8 + 4];
            float4 b0 = *(const float4*)&Vs[kk][tx * 8];
            float4 b1 = *(const float4*)&Vs[kk][tx * 8 + 4];
            const float a[8]  = {a0.x, a0.y, a0.z, a0.w, a1.x, a1.y, a1.z, a1.w};
            const float bw[8] = {b0.x, b0.y, b0.z, b0.w, b1.x, b1.y, b1.z, b1.w};
            #pragma unroll
            for (int i = 0; i < 8; i++)
                #pragma unroll
                for (int j = 0; j < 8; j++) acc[i][j] += a[i] * bw[j];
        }
        __syncthreads();
    }

    const int jj0 = tx * 8;
    const int c = hh * DD + (jj0 & 63);
    #pragma unroll
    for (int i = 0; i < 8; i++) {
        int qi = q0 + ty * 8 + i;
        if (qi >= N1) continue;
        float sc = g_inv[bh * N1 + qi];
        int row = (jj0 < 64) ? qi : (N1 + qi);
        float4 o0, o1;
        o0.x = acc[i][0] * sc; o0.y = acc[i][1] * sc;
        o0.z = acc[i][2] * sc; o0.w = acc[i][3] * sc;
        o1.x = acc[i][4] * sc; o1.y = acc[i][5] * sc;
        o1.z = acc[i][6] * sc; o1.w = acc[i][7] * sc;
        float* dst = &g_O[((size_t)b * M_TOT + row) * CC + c];
        *(float4*)dst       = o0;
        *(float4*)(dst + 4) = o1;
    }
}

// ------------------------------------------------------------------
// 5) output projection via bf16 mma: grid (3, 65)
// ------------------------------------------------------------------
__global__ __launch_bounds__(256)
void final_kernel(const float* __restrict__ Wo,
                  const float* __restrict__ bo,
                  float* __restrict__ out) {
    __shared__ __nv_bfloat16 Ah[128][KST], Al[128][KST];
    __shared__ __nv_bfloat16 Bh[128][KST], Bl[128][KST];

    const int m0 = blockIdx.y * 128, n0 = blockIdx.x * 128;
    const int tid  = threadIdx.x;
    const int warp = tid >> 5, lane = tid & 31;
    const int wm = warp >> 2, wn = warp & 3;
    const int g = lane >> 2, t = lane & 3;

    float d[4][4][4];
    #pragma unroll
    for (int i = 0; i < 4; i++)
        #pragma unroll
        for (int j = 0; j < 4; j++)
            #pragma unroll
            for (int r = 0; r < 4; r++) d[i][j][r] = 0.f;

    const uint32_t* Ah32 = (const uint32_t*)&Ah[0][0];
    const uint32_t* Al32 = (const uint32_t*)&Al[0][0];
    const uint32_t* Bh32 = (const uint32_t*)&Bh[0][0];
    const uint32_t* Bl32 = (const uint32_t*)&Bl[0][0];

    for (int k0 = 0; k0 < CC; k0 += 32) {
        #pragma unroll
        for (int it = 0; it < 8; it++) {
            int slot = tid + it * 256;
            int ml = slot >> 4, kp = slot & 15;
            int m = m0 + ml;
            float2 f = make_float2(0.f, 0.f);
            if (m < MROWS2)
                f = *(const float2*)&g_O[(size_t)m * CC + k0 + 2 * kp];
            __nv_bfloat162 hi, lo;
            bf16_split2(f, &hi, &lo);
            *(__nv_bfloat162*)&Ah[ml][2 * kp] = hi;
            *(__nv_bfloat162*)&Al[ml][2 * kp] = lo;
        }
        #pragma unroll
        for (int it = 0; it < 8; it++) {
            int slot = tid + it * 256;
            int nl = slot & 127, kp = slot >> 7;
            float2 f;
            f.x = Wo[(size_t)(k0 + 2 * kp)     * CC + n0 + nl];
            f.y = Wo[(size_t)(k0 + 2 * kp + 1) * CC + n0 + nl];
            __nv_bfloat162 hi, lo;
            bf16_split2(f, &hi, &lo);
            *(__nv_bfloat162*)&Bh[nl][2 * kp] = hi;
            *(__nv_bfloat162*)&Bl[nl][2 * kp] = lo;
        }
        __syncthreads();

        #pragma unroll
        for (int ks = 0; ks < 2; ks++) {
            const int ko = ks * 8;
            uint32_t bh[4][2], bl[4][2];
            #pragma unroll
            for (int nt = 0; nt < 4; nt++) {
                int nb = (wn * 32 + nt * 8 + g) * KSTU + ko + t;
                bh[nt][0] = Bh32[nb];     bh[nt][1] = Bh32[nb + 4];
                bl[nt][0] = Bl32[nb];     bl[nt][1] = Bl32[nb + 4];
            }
            #pragma unroll
            for (int mt = 0; mt < 4; mt++) {
                int ab = (wm * 64 + mt * 16 + g) * KSTU + ko + t;
                uint32_t ah0 = Ah32[ab],            ah1 = Ah32[ab + 8 * KSTU];
                uint32_t ah2 = Ah32[ab + 4],        ah3 = Ah32[ab + 4 + 8 * KSTU];
                uint32_t al0 = Al32[ab],            al1 = Al32[ab + 8 * KSTU];
                uint32_t al2 = Al32[ab + 4],        al3 = Al32[ab + 4 + 8 * KSTU];
                #pragma unroll
                for (int nt = 0; nt < 4; nt++) {
                    mma_bf16(d[mt][nt], ah0, ah1, ah2, ah3, bh[nt][0], bh[nt][1]);
                    mma_bf16(d[mt][nt], ah0, ah1, ah2, ah3, bl[nt][0], bl[nt][1]);
                    mma_bf16(d[mt][nt], al0, al1, al2, al3, bh[nt][0], bh[nt][1]);
                }
            }
        }
        __syncthreads();
    }

    #pragma unroll
    for (int mt = 0; mt < 4; mt++) {
        #pragma unroll
        for (int nt = 0; nt < 4; nt++) {
            int m = m0 + wm * 64 + mt * 16 + g;
            int c = n0 + wn * 32 + nt * 8 + 2 * t;
            float b0v = bo[c], b1v = bo[c + 1];
            if (m < MROWS2) {
                float2 o; o.x = d[mt][nt][0] + b0v; o.y = d[mt][nt][1] + b1v;
                *(float2*)&out[(size_t)m * CC + c] = o;
            }
            if (m + 8 < MROWS2) {
                float2 o; o.x = d[mt][nt][2] + b0v; o.y = d[mt][nt][3] + b1v;
                *(float2*)&out[(size_t)(m + 8) * CC + c] = o;
            }
        }
    }
}

// ------------------------------------------------------------------
extern "C" void kernel_launch(void* const* d_in, const int* in_sizes, int n_in,
                              void* d_out, int out_size) {
    const float* x   = (const float*)d_in[0];
    const float* Wq1 = (const float*)d_in[1];  const float* bq1 = (const float*)d_in[2];
    const float* Wq2 = (const float*)d_in[3];  const float* bq2 = (const float*)d_in[4];
    const float* Wk1 = (const float*)d_in[5];  const float* bk1 = (const float*)d_in[6];
    const float* Wk2 = (const float*)d_in[7];  const float* bk2 = (const float*)d_in[8];
    const float* Wv1 = (const float*)d_in[9];  const float* bv1 = (const float*)d_in[10];
    const float* Wv2 = (const float*)d_in[11]; const float* bv2 = (const float*)d_in[12];
    const float* Wo  = (const float*)d_in[13]; const float* bo  = (const float*)d_in[14];
    const float* wts = (const float*)d_in[15]; const float* gum = (const float*)d_in[16];
    float* out = (float*)d_out;

    select_kernel<<<1, 1>>>(wts, gum);

    dim3 pg(CC / 128, (MROWS + 127) / 128, 4);              // 3 x 33 x 4
    proj_kernel<<<pg, 256>>>(x, Wq1, bq1, Wq2, bq2, Wk1, bk1, Wk2, bk2,
                             Wv1, bv1, Wv2, bv2);

    dim3 sg((N1 + 63) / 64, (N1 + 63) / 64, BHN);           // 9 x 9 x 48
    scores_kernel<<<sg, 256>>>();

    softmax_kernel<<<BHN * N1, 128>>>();

    av_kernel<<<dim3((N1 + 127) / 128, BHN), 256>>>();      // 5 x 48

    final_kernel<<<dim3(CC / 128, (MROWS2 + 127) / 128, 1), 256>>>(Wo, bo, out);
}

// round 10
// speedup vs baseline: 1.7844x; 1.1412x over previous
#include <cuda_runtime.h>
#include <cuda_bf16.h>
#include <stdint.h>
#include <math.h>

#define BB     8
#define M_TOT  1026
#define CC     384
#define N1     513
#define HH     6
#define DD     64
#define BHN    (BB*HH)      // 48
#define MROWS  (BB*N1)      // 4104
#define MROWS2 (BB*M_TOT)   // 8208

// ---- scratch (device globals; no cudaMalloc allowed) ----
__device__ int   g_sel;
__device__ float g_Q [MROWS*CC];
__device__ float g_K [MROWS*CC];
__device__ float g_V1[MROWS*CC];
__device__ float g_V2[MROWS*CC];
__device__ float g_S [(size_t)BHN*N1*N1];   // scores -> exp'd scores (~50.5MB, L2)
__device__ float g_inv[BHN*N1];             // 1/rowsum
__device__ float g_O [MROWS2*CC];           // pre-Wo activations

// ------------------------------------------------------------------
// 0) straight-through gumbel selection: argmax(weights + noise)
// ------------------------------------------------------------------
__global__ void select_kernel(const float* __restrict__ w,
                              const float* __restrict__ g) {
    float best = w[0] + g[0];
    int bi = 0;
    #pragma unroll
    for (int i = 1; i < 4; i++) {
        float v = w[i] + g[i];
        if (v > best) { best = v; bi = i; }
    }
    g_sel = bi;
}

// ==================================================================
// bf16 3-pass (hi/lo split) tensor-core GEMM common pieces
//   BM=128 BN=128 BK=32, 256 threads (8 warps = 2m x 4n), warp=64x32
// ==================================================================
#define KST 34          // bf16 row stride (17 u32)
#define KSTU 17         // u32 row stride

__device__ __forceinline__ void bf16_split2(float2 f, __nv_bfloat162* hi, __nv_bfloat162* lo) {
    __nv_bfloat16 hx = __float2bfloat16(f.x);
    __nv_bfloat16 hy = __float2bfloat16(f.y);
    __nv_bfloat16 lx = __float2bfloat16(f.x - __bfloat162float(hx));
    __nv_bfloat16 ly = __float2bfloat16(f.y - __bfloat162float(hy));
    hi->x = hx; hi->y = hy;
    lo->x = lx; lo->y = ly;
}

__device__ __forceinline__ void mma_bf16(float* d, uint32_t a0, uint32_t a1,
                                         uint32_t a2, uint32_t a3,
                                         uint32_t b0, uint32_t b1) {
    asm volatile(
        "mma.sync.aligned.m16n8k16.row.col.f32.bf16.bf16.f32 "
        "{%0,%1,%2,%3},{%4,%5,%6,%7},{%8,%9},{%0,%1,%2,%3};"
        : "+f"(d[0]), "+f"(d[1]), "+f"(d[2]), "+f"(d[3])
        : "r"(a0), "r"(a1), "r"(a2), "r"(a3), "r"(b0), "r"(b1));
}

// inner-loop macro body (shared by all four mma kernels)
#define MMA_TILE_LOOP(Ah32, Al32, Bh32, Bl32, d, wm, wn, g, t)                      \
    _Pragma("unroll")                                                               \
    for (int ks = 0; ks < 2; ks++) {                                                \
        const int ko = ks * 8;                                                      \
        uint32_t bh_[4][2], bl_[4][2];                                              \
        _Pragma("unroll")                                                           \
        for (int nt = 0; nt < 4; nt++) {                                            \
            int nb = ((wn) * 32 + nt * 8 + (g)) * KSTU + ko + (t);                  \
            bh_[nt][0] = Bh32[nb];     bh_[nt][1] = Bh32[nb + 4];                   \
            bl_[nt][0] = Bl32[nb];     bl_[nt][1] = Bl32[nb + 4];                   \
        }                                                                           \
        _Pragma("unroll")                                                           \
        for (int mt = 0; mt < 4; mt++) {                                            \
            int ab = ((wm) * 64 + mt * 16 + (g)) * KSTU + ko + (t);                 \
            uint32_t ah0 = Ah32[ab],     ah1 = Ah32[ab + 8 * KSTU];                 \
            uint32_t ah2 = Ah32[ab + 4], ah3 = Ah32[ab + 4 + 8 * KSTU];             \
            uint32_t al0 = Al32[ab],     al1 = Al32[ab + 8 * KSTU];                 \
            uint32_t al2 = Al32[ab + 4], al3 = Al32[ab + 4 + 8 * KSTU];             \
            _Pragma("unroll")                                                       \
            for (int nt = 0; nt < 4; nt++) {                                        \
                mma_bf16(d[mt][nt], ah0, ah1, ah2, ah3, bh_[nt][0], bh_[nt][1]);    \
                mma_bf16(d[mt][nt], ah0, ah1, ah2, ah3, bl_[nt][0], bl_[nt][1]);    \
                mma_bf16(d[mt][nt], al0, al1, al2, al3, bh_[nt][0], bh_[nt][1]);    \
            }                                                                       \
        }                                                                           \
    }

// ------------------------------------------------------------------
// 1) input projections via bf16 mma: 4 jobs, grid (3, 33, 4)
// ------------------------------------------------------------------
__global__ __launch_bounds__(256)
void proj_kernel(const float* __restrict__ x,
                 const float* Wq1, const float* bq1,
                 const float* Wq2, const float* bq2,
                 const float* Wk1, const float* bk1,
                 const float* Wk2, const float* bk2,
                 const float* Wv1, const float* bv1,
                 const float* Wv2, const float* bv2) {
    const int job = blockIdx.z;
    const int sel = g_sel;
    const float* W; const float* bias; float* OUT; int off;
    if (job == 0) { int qs = sel >> 1; W = qs ? Wq2 : Wq1; bias = qs ? bq2 : bq1; OUT = g_Q;  off = qs ? N1 : 0; }
    else if (job == 1) { int ks = sel & 1; W = ks ? Wk2 : Wk1; bias = ks ? bk2 : bk1; OUT = g_K;  off = ks ? N1 : 0; }
    else if (job == 2) { W = Wv1; bias = bv1; OUT = g_V1; off = 0;  }
    else               { W = Wv2; bias = bv2; OUT = g_V2; off = N1; }

    __shared__ __nv_bfloat16 Ah[128][KST], Al[128][KST];
    __shared__ __nv_bfloat16 Bh[128][KST], Bl[128][KST];

    const int m0 = blockIdx.y * 128, n0 = blockIdx.x * 128;
    const int tid  = threadIdx.x;
    const int warp = tid >> 5, lane = tid & 31;
    const int wm = warp >> 2, wn = warp & 3;
    const int g = lane >> 2, t = lane & 3;

    float d[4][4][4];
    #pragma unroll
    for (int i = 0; i < 4; i++)
        #pragma unroll
        for (int j = 0; j < 4; j++)
            #pragma unroll
            for (int r = 0; r < 4; r++) d[i][j][r] = 0.f;

    const uint32_t* Ah32 = (const uint32_t*)&Ah[0][0];
    const uint32_t* Al32 = (const uint32_t*)&Al[0][0];
    const uint32_t* Bh32 = (const uint32_t*)&Bh[0][0];
    const uint32_t* Bl32 = (const uint32_t*)&Bl[0][0];

    for (int k0 = 0; k0 < CC; k0 += 32) {
        #pragma unroll
        for (int it = 0; it < 8; it++) {
            int slot = tid + it * 256;
            int ml = slot >> 4, kp = slot & 15;
            int m = m0 + ml;
            float2 f = make_float2(0.f, 0.f);
            if (m < MROWS) {
                int b = m / N1, n = m % N1;
                f = *(const float2*)&x[((size_t)b * M_TOT + n + off) * CC + k0 + 2 * kp];
            }
            __nv_bfloat162 hi, lo;
            bf16_split2(f, &hi, &lo);
            *(__nv_bfloat162*)&Ah[ml][2 * kp] = hi;
            *(__nv_bfloat162*)&Al[ml][2 * kp] = lo;
        }
        #pragma unroll
        for (int it = 0; it < 8; it++) {
            int slot = tid + it * 256;
            int nl = slot & 127, kp = slot >> 7;
            float2 f;
            f.x = W[(size_t)(k0 + 2 * kp)     * CC + n0 + nl];
            f.y = W[(size_t)(k0 + 2 * kp + 1) * CC + n0 + nl];
            __nv_bfloat162 hi, lo;
            bf16_split2(f, &hi, &lo);
            *(__nv_bfloat162*)&Bh[nl][2 * kp] = hi;
            *(__nv_bfloat162*)&Bl[nl][2 * kp] = lo;
        }
        __syncthreads();
        MMA_TILE_LOOP(Ah32, Al32, Bh32, Bl32, d, wm, wn, g, t)
        __syncthreads();
    }

    #pragma unroll
    for (int mt = 0; mt < 4; mt++) {
        #pragma unroll
        for (int nt = 0; nt < 4; nt++) {
            int m = m0 + wm * 64 + mt * 16 + g;
            int c = n0 + wn * 32 + nt * 8 + 2 * t;
            float b0v = bias[c], b1v = bias[c + 1];
            if (m < MROWS) {
                float2 o; o.x = d[mt][nt][0] + b0v; o.y = d[mt][nt][1] + b1v;
                *(float2*)&OUT[(size_t)m * CC + c] = o;
            }
            if (m + 8 < MROWS) {
                float2 o; o.x = d[mt][nt][2] + b0v; o.y = d[mt][nt][3] + b1v;
                *(float2*)&OUT[(size_t)(m + 8) * CC + c] = o;
            }
        }
    }
}

// ------------------------------------------------------------------
// 2) scores via bf16 mma: S = scale * Q Kt, grid (5, 5, 48)
//    K-dim = DD = 64 (two 32-chunks). A and B staged identically.
// ------------------------------------------------------------------
__global__ __launch_bounds__(256)
void scores_kernel() {
    const int bh = blockIdx.z;
    const int b = bh / HH, hh = bh % HH;
    const int m0 = blockIdx.y * 128, n0 = blockIdx.x * 128;

    __shared__ __nv_bfloat16 Ah[128][KST], Al[128][KST];
    __shared__ __nv_bfloat16 Bh[128][KST], Bl[128][KST];

    const int tid  = threadIdx.x;
    const int warp = tid >> 5, lane = tid & 31;
    const int wm = warp >> 2, wn = warp & 3;
    const int g = lane >> 2, t = lane & 3;

    float d[4][4][4];
    #pragma unroll
    for (int i = 0; i < 4; i++)
        #pragma unroll
        for (int j = 0; j < 4; j++)
            #pragma unroll
            for (int r = 0; r < 4; r++) d[i][j][r] = 0.f;

    const uint32_t* Ah32 = (const uint32_t*)&Ah[0][0];
    const uint32_t* Al32 = (const uint32_t*)&Al[0][0];
    const uint32_t* Bh32 = (const uint32_t*)&Bh[0][0];
    const uint32_t* Bl32 = (const uint32_t*)&Bl[0][0];

    #pragma unroll
    for (int k0 = 0; k0 < DD; k0 += 32) {
        // A: Q rows (row-major, contiguous d) — coalesced float2
        #pragma unroll
        for (int it = 0; it < 8; it++) {
            int slot = tid + it * 256;
            int ml = slot >> 4, kp = slot & 15;
            int qi = m0 + ml;
            float2 f = make_float2(0.f, 0.f);
            if (qi < N1)
                f = *(const float2*)&g_Q[((size_t)b * N1 + qi) * CC + hh * DD + k0 + 2 * kp];
            __nv_bfloat162 hi, lo;
            bf16_split2(f, &hi, &lo);
            *(__nv_bfloat162*)&Ah[ml][2 * kp] = hi;
            *(__nv_bfloat162*)&Al[ml][2 * kp] = lo;
        }
        // B: K rows (row-major, contiguous d) — same pattern
        #pragma unroll
        for (int it = 0; it < 8; it++) {
            int slot = tid + it * 256;
            int nl = slot >> 4, kp = slot & 15;
            int kj = n0 + nl;
            float2 f = make_float2(0.f, 0.f);
            if (kj < N1)
                f = *(const float2*)&g_K[((size_t)b * N1 + kj) * CC + hh * DD + k0 + 2 * kp];
            __nv_bfloat162 hi, lo;
            bf16_split2(f, &hi, &lo);
            *(__nv_bfloat162*)&Bh[nl][2 * kp] = hi;
            *(__nv_bfloat162*)&Bl[nl][2 * kp] = lo;
        }
        __syncthreads();
        MMA_TILE_LOOP(Ah32, Al32, Bh32, Bl32, d, wm, wn, g, t)
        __syncthreads();
    }

    const float scale = 0.125f;  // 64^-0.5
    const size_t base = (size_t)bh * N1 * N1;
    #pragma unroll
    for (int mt = 0; mt < 4; mt++) {
        #pragma unroll
        for (int nt = 0; nt < 4; nt++) {
            int qi = m0 + wm * 64 + mt * 16 + g;
            int kj = n0 + wn * 32 + nt * 8 + 2 * t;
            if (qi < N1) {
                if (kj     < N1) g_S[base + (size_t)qi * N1 + kj]     = d[mt][nt][0] * scale;
                if (kj + 1 < N1) g_S[base + (size_t)qi * N1 + kj + 1] = d[mt][nt][1] * scale;
            }
            if (qi + 8 < N1) {
                if (kj     < N1) g_S[base + (size_t)(qi + 8) * N1 + kj]     = d[mt][nt][2] * scale;
                if (kj + 1 < N1) g_S[base + (size_t)(qi + 8) * N1 + kj + 1] = d[mt][nt][3] * scale;
            }
        }
    }
}

// ------------------------------------------------------------------
// 3) softmax: row cached in regs -> 1 read + 1 write of g_S.
// ------------------------------------------------------------------
__global__ __launch_bounds__(128)
void softmax_kernel() {
    const int row = blockIdx.x;
    float* p = g_S + (size_t)row * N1;
    const int t = threadIdx.x;
    __shared__ float redm[4];
    __shared__ float reds[4];

    float v[5];
    float m = -1e30f;
    #pragma unroll
    for (int c = 0; c < 5; c++) {
        int j = t + c * 128;
        v[c] = (j < N1) ? p[j] : -1e30f;
        m = fmaxf(m, v[c]);
    }
    #pragma unroll
    for (int o = 16; o > 0; o >>= 1) m = fmaxf(m, __shfl_xor_sync(0xffffffffu, m, o));
    if ((t & 31) == 0) redm[t >> 5] = m;
    __syncthreads();
    m = fmaxf(fmaxf(redm[0], redm[1]), fmaxf(redm[2], redm[3]));

    float s = 0.f;
    #pragma unroll
    for (int c = 0; c < 5; c++) {
        int j = t + c * 128;
        if (j < N1) {
            float e = __expf(v[c] - m);
            p[j] = e;
            s += e;
        }
    }
    #pragma unroll
    for (int o = 16; o > 0; o >>= 1) s += __shfl_xor_sync(0xffffffffu, s, o);
    if ((t & 31) == 0) reds[t >> 5] = s;
    __syncthreads();
    if (t == 0) g_inv[row] = 1.f / (reds[0] + reds[1] + reds[2] + reds[3]);
}

// ------------------------------------------------------------------
// 4) AV via bf16 mma: O = expS @ [V1|V2], * 1/sum at epilogue
//    grid (5, 48); K-dim 544 (17 chunks of 32)
// ------------------------------------------------------------------
__global__ __launch_bounds__(256)
void av_kernel() {
    const int bh = blockIdx.y;
    const int b = bh / HH, hh = bh % HH;
    const int m0 = blockIdx.x * 128;

    __shared__ __nv_bfloat16 Ah[128][KST], Al[128][KST];
    __shared__ __nv_bfloat16 Bh[128][KST], Bl[128][KST];

    const int tid  = threadIdx.x;
    const int warp = tid >> 5, lane = tid & 31;
    const int wm = warp >> 2, wn = warp & 3;
    const int g = lane >> 2, t = lane & 3;
    const size_t Sbase = (size_t)bh * N1 * N1;

    float d[4][4][4];
    #pragma unroll
    for (int i = 0; i < 4; i++)
        #pragma unroll
        for (int j = 0; j < 4; j++)
            #pragma unroll
            for (int r = 0; r < 4; r++) d[i][j][r] = 0.f;

    const uint32_t* Ah32 = (const uint32_t*)&Ah[0][0];
    const uint32_t* Al32 = (const uint32_t*)&Al[0][0];
    const uint32_t* Bh32 = (const uint32_t*)&Bh[0][0];
    const uint32_t* Bl32 = (const uint32_t*)&Bl[0][0];

    for (int k0 = 0; k0 < 544; k0 += 32) {
        // A: expS rows (stride 513, odd -> scalar loads)
        #pragma unroll
        for (int it = 0; it < 8; it++) {
            int slot = tid + it * 256;
            int ml = slot >> 4, kp = slot & 15;
            int qi = m0 + ml, ki = k0 + 2 * kp;
            float2 f = make_float2(0.f, 0.f);
            if (qi < N1) {
                const float* p = &g_S[Sbase + (size_t)qi * N1 + ki];
                if (ki     < N1) f.x = p[0];
                if (ki + 1 < N1) f.y = p[1];
            }
            __nv_bfloat162 hi, lo;
            bf16_split2(f, &hi, &lo);
            *(__nv_bfloat162*)&Ah[ml][2 * kp] = hi;
            *(__nv_bfloat162*)&Al[ml][2 * kp] = lo;
        }
        // B transposed: [n=j][k=ki]; j<64 -> V1, j>=64 -> V2
        #pragma unroll
        for (int it = 0; it < 8; it++) {
            int slot = tid + it * 256;
            int nl = slot & 127, kp = slot >> 7;
            int ki = k0 + 2 * kp;
            int col = hh * DD + (nl & 63);
            const float* V = (nl < 64) ? g_V1 : g_V2;
            float2 f = make_float2(0.f, 0.f);
            if (ki     < N1) f.x = V[((size_t)b * N1 + ki)     * CC + col];
            if (ki + 1 < N1) f.y = V[((size_t)b * N1 + ki + 1) * CC + col];
            __nv_bfloat162 hi, lo;
            bf16_split2(f, &hi, &lo);
            *(__nv_bfloat162*)&Bh[nl][2 * kp] = hi;
            *(__nv_bfloat162*)&Bl[nl][2 * kp] = lo;
        }
        __syncthreads();
        MMA_TILE_LOOP(Ah32, Al32, Bh32, Bl32, d, wm, wn, g, t)
        __syncthreads();
    }

    #pragma unroll
    for (int mt = 0; mt < 4; mt++) {
        #pragma unroll
        for (int nt = 0; nt < 4; nt++) {
            int qi = m0 + wm * 64 + mt * 16 + g;
            int c = wn * 32 + nt * 8 + 2 * t;                 // 0..126
            int row_off = (c < 64) ? 0 : N1;
            int ci = hh * DD + (c & 63);
            if (qi < N1) {
                float sc = g_inv[bh * N1 + qi];
                float2 o; o.x = d[mt][nt][0] * sc; o.y = d[mt][nt][1] * sc;
                *(float2*)&g_O[((size_t)b * M_TOT + row_off + qi) * CC + ci] = o;
            }
            if (qi + 8 < N1) {
                float sc = g_inv[bh * N1 + qi + 8];
                float2 o; o.x = d[mt][nt][2] * sc; o.y = d[mt][nt][3] * sc;
                *(float2*)&g_O[((size_t)b * M_TOT + row_off + qi + 8) * CC + ci] = o;
            }
        }
    }
}

// ------------------------------------------------------------------
// 5) output projection via bf16 mma: grid (3, 65)
// ------------------------------------------------------------------
__global__ __launch_bounds__(256)
void final_kernel(const float* __restrict__ Wo,
                  const float* __restrict__ bo,
                  float* __restrict__ out) {
    __shared__ __nv_bfloat16 Ah[128][KST], Al[128][KST];
    __shared__ __nv_bfloat16 Bh[128][KST], Bl[128][KST];

    const int m0 = blockIdx.y * 128, n0 = blockIdx.x * 128;
    const int tid  = threadIdx.x;
    const int warp = tid >> 5, lane = tid & 31;
    const int wm = warp >> 2, wn = warp & 3;
    const int g = lane >> 2, t = lane & 3;

    float d[4][4][4];
    #pragma unroll
    for (int i = 0; i < 4; i++)
        #pragma unroll
        for (int j = 0; j < 4; j++)
            #pragma unroll
            for (int r = 0; r < 4; r++) d[i][j][r] = 0.f;

    const uint32_t* Ah32 = (const uint32_t*)&Ah[0][0];
    const uint32_t* Al32 = (const uint32_t*)&Al[0][0];
    const uint32_t* Bh32 = (const uint32_t*)&Bh[0][0];
    const uint32_t* Bl32 = (const uint32_t*)&Bl[0][0];

    for (int k0 = 0; k0 < CC; k0 += 32) {
        #pragma unroll
        for (int it = 0; it < 8; it++) {
            int slot = tid + it * 256;
            int ml = slot >> 4, kp = slot & 15;
            int m = m0 + ml;
            float2 f = make_float2(0.f, 0.f);
            if (m < MROWS2)
                f = *(const float2*)&g_O[(size_t)m * CC + k0 + 2 * kp];
            __nv_bfloat162 hi, lo;
            bf16_split2(f, &hi, &lo);
            *(__nv_bfloat162*)&Ah[ml][2 * kp] = hi;
            *(__nv_bfloat162*)&Al[ml][2 * kp] = lo;
        }
        #pragma unroll
        for (int it = 0; it < 8; it++) {
            int slot = tid + it * 256;
            int nl = slot & 127, kp = slot >> 7;
            float2 f;
            f.x = Wo[(size_t)(k0 + 2 * kp)     * CC + n0 + nl];
            f.y = Wo[(size_t)(k0 + 2 * kp + 1) * CC + n0 + nl];
            __nv_bfloat162 hi, lo;
            bf16_split2(f, &hi, &lo);
            *(__nv_bfloat162*)&Bh[nl][2 * kp] = hi;
            *(__nv_bfloat162*)&Bl[nl][2 * kp] = lo;
        }
        __syncthreads();
        MMA_TILE_LOOP(Ah32, Al32, Bh32, Bl32, d, wm, wn, g, t)
        __syncthreads();
    }

    #pragma unroll
    for (int mt = 0; mt < 4; mt++) {
        #pragma unroll
        for (int nt = 0; nt < 4; nt++) {
            int m = m0 + wm * 64 + mt * 16 + g;
            int c = n0 + wn * 32 + nt * 8 + 2 * t;
            float b0v = bo[c], b1v = bo[c + 1];
            if (m < MROWS2) {
                float2 o; o.x = d[mt][nt][0] + b0v; o.y = d[mt][nt][1] + b1v;
                *(float2*)&out[(size_t)m * CC + c] = o;
            }
            if (m + 8 < MROWS2) {
                float2 o; o.x = d[mt][nt][2] + b0v; o.y = d[mt][nt][3] + b1v;
                *(float2*)&out[(size_t)(m + 8) * CC + c] = o;
            }
        }
    }
}

// ------------------------------------------------------------------
extern "C" void kernel_launch(void* const* d_in, const int* in_sizes, int n_in,
                              void* d_out, int out_size) {
    const float* x   = (const float*)d_in[0];
    const float* Wq1 = (const float*)d_in[1];  const float* bq1 = (const float*)d_in[2];
    const float* Wq2 = (const float*)d_in[3];  const float* bq2 = (const float*)d_in[4];
    const float* Wk1 = (const float*)d_in[5];  const float* bk1 = (const float*)d_in[6];
    const float* Wk2 = (const float*)d_in[7];  const float* bk2 = (const float*)d_in[8];
    const float* Wv1 = (const float*)d_in[9];  const float* bv1 = (const float*)d_in[10];
    const float* Wv2 = (const float*)d_in[11]; const float* bv2 = (const float*)d_in[12];
    const float* Wo  = (const float*)d_in[13]; const float* bo  = (const float*)d_in[14];
    const float* wts = (const float*)d_in[15]; const float* gum = (const float*)d_in[16];
    float* out = (float*)d_out;

    select_kernel<<<1, 1>>>(wts, gum);

    dim3 pg(CC / 128, (MROWS + 127) / 128, 4);              // 3 x 33 x 4
    proj_kernel<<<pg, 256>>>(x, Wq1, bq1, Wq2, bq2, Wk1, bk1, Wk2, bk2,
                             Wv1, bv1, Wv2, bv2);

    dim3 sg((N1 + 127) / 128, (N1 + 127) / 128, BHN);       // 5 x 5 x 48
    scores_kernel<<<sg, 256>>>();

    softmax_kernel<<<BHN * N1, 128>>>();

    av_kernel<<<dim3((N1 + 127) / 128, BHN), 256>>>();      // 5 x 48

    final_kernel<<<dim3(CC / 128, (MROWS2 + 127) / 128, 1), 256>>>(Wo, bo, out);
}